// round 1
// baseline (speedup 1.0000x reference)
#include <cuda_runtime.h>
#include <cuda_bf16.h>
#include <cstdint>

// ---------------- problem constants ----------------
#define NB     65536
#define IN1    384
#define IN2    128
#define KDIM   512      // IN1+IN2
#define G1U    384      // GRU1 units
#define N1     1152     // 3*G1U
#define G2U    16       // GRU2 units
#define NLEV   256

typedef unsigned long long u64;

// ---------------- scratch (no allocations allowed) ----------------
__device__ float g_h1[(size_t)NB * G1U];   // 96 MB
__device__ float g_h2[(size_t)NB * G2U];   // 4 MB

// ---------------- packed f32x2 helpers ----------------
__device__ __forceinline__ u64 ffma2(u64 a, u64 b, u64 c) {
    u64 d;
    asm("fma.rn.f32x2 %0, %1, %2, %3;" : "=l"(d) : "l"(a), "l"(b), "l"(c));
    return d;
}
__device__ __forceinline__ float2 unpack2(u64 v) {
    float2 r;
    asm("mov.b64 {%0, %1}, %2;" : "=f"(r.x), "=f"(r.y) : "l"(v));
    return r;
}
__device__ __forceinline__ float sigmoid_f(float x) {
    return 1.0f / (1.0f + __expf(-x));
}

// =====================================================================
// Kernel 1: h1 = GRU1(concat(x1,x2), h=0)
// GEMM [65536,512] x [512,1152] fused with gate nonlinearity.
// Block tile: 128 rows x 32 j-columns (covers z/r/h gates -> 96 N cols).
// Thread: 8 rows (4 packed row-pairs... actually j-packed) -- layout:
//   tx (0..15) selects a j-pair (j0+2tx, j0+2tx+1), ty (0..15) selects 8 rows.
//   A stored DUPLICATED in smem: As[k][2m]=As[k][2m+1]=a  -> LDS.64 gives (a,a)
//   B loaded as natural float2 over adjacent j -> (bj0,bj1)
//   acc[gate][m] = f32x2 packed over the two j's.  24 FFMA2 per k per thread.
// =====================================================================
__global__ __launch_bounds__(256, 2)
void gemm1_kernel(const float* __restrict__ x1, const float* __restrict__ x2,
                  const float* __restrict__ W,  const float* __restrict__ bias)
{
    __shared__ float Asd[16][258];  // duplicated A: [k][2*m + {0,1}], stride 258 (bank-safe)
    __shared__ float Bs[16][96];    // [k][seg*32 + jj]

    const int t  = threadIdx.x;
    const int tx = t & 15;          // j-pair index
    const int ty = t >> 4;          // row-group index (8 rows each)
    const int j0 = blockIdx.x * 32;
    const int m0 = blockIdx.y * 128;

    u64 accz[8], accr[8], acch[8];
#pragma unroll
    for (int m = 0; m < 8; ++m) { accz[m] = 0ull; accr[m] = 0ull; acch[m] = 0ull; }

    for (int kt = 0; kt < 32; ++kt) {
        const int k0 = kt * 16;
        // ---- load A tile (duplicated) ----
        const float* src;
        int ncol, kbase;
        if (k0 < IN1) { src = x1; ncol = IN1; kbase = k0; }
        else          { src = x2; ncol = IN2; kbase = k0 - IN1; }
        __syncthreads();
#pragma unroll
        for (int it = 0; it < 8; ++it) {
            int idx = t + it * 256;          // 0..2047
            int m   = idx >> 4;              // row within tile
            int kk  = idx & 15;
            float v = src[(size_t)(m0 + m) * ncol + kbase + kk];
            float2 vv = make_float2(v, v);
            *(float2*)&Asd[kk][2 * m] = vv;  // STS.64, conflict-free (stride 258)
        }
        // ---- load B tile: cols {j0..j0+31, 384+j0.., 768+j0..} ----
#pragma unroll
        for (int it = 0; it < 6; ++it) {
            int idx = t + it * 256;          // 0..1535
            int kk  = idx / 96;
            int c   = idx % 96;
            int seg = c >> 5;
            int jj  = c & 31;
            Bs[kk][c] = W[(size_t)(k0 + kk) * N1 + seg * G1U + j0 + jj];
        }
        __syncthreads();
        // ---- compute ----
#pragma unroll
        for (int k = 0; k < 16; ++k) {
            const u64 bz = *(const u64*)&Bs[k][2 * tx];
            const u64 br = *(const u64*)&Bs[k][32 + 2 * tx];
            const u64 bh = *(const u64*)&Bs[k][64 + 2 * tx];
#pragma unroll
            for (int m = 0; m < 8; ++m) {
                const u64 a2 = *(const u64*)&Asd[k][(ty * 8 + m) * 2];
                accz[m] = ffma2(a2, bz, accz[m]);
                accr[m] = ffma2(a2, br, accr[m]);
                acch[m] = ffma2(a2, bh, acch[m]);
            }
        }
    }

    // ---- fused GRU gate epilogue (h=0  =>  h1 = (1-z)*hcand) ----
    const int j = j0 + 2 * tx;
    // input bias (row 0) and recurrent bias (row 1) for both j lanes, 3 gates
    const float b0z0 = bias[j],            b0z1 = bias[j + 1];
    const float b0r0 = bias[G1U + j],      b0r1 = bias[G1U + j + 1];
    const float b0h0 = bias[2 * G1U + j],  b0h1 = bias[2 * G1U + j + 1];
    const float b1z0 = bias[N1 + j],           b1z1 = bias[N1 + j + 1];
    const float b1r0 = bias[N1 + G1U + j],     b1r1 = bias[N1 + G1U + j + 1];
    const float b1h0 = bias[N1 + 2 * G1U + j], b1h1 = bias[N1 + 2 * G1U + j + 1];

#pragma unroll
    for (int m = 0; m < 8; ++m) {
        const int row = m0 + ty * 8 + m;
        float2 az = unpack2(accz[m]);
        float2 ar = unpack2(accr[m]);
        float2 ah = unpack2(acch[m]);

        float z0 = sigmoid_f(az.x + b0z0 + b1z0);
        float r0 = sigmoid_f(ar.x + b0r0 + b1r0);
        float c0 = tanhf(ah.x + b0h0 + r0 * b1h0);
        float h0 = (1.0f - z0) * c0;

        float z1 = sigmoid_f(az.y + b0z1 + b1z1);
        float r1 = sigmoid_f(ar.y + b0r1 + b1r1);
        float c1 = tanhf(ah.y + b0h1 + r1 * b1h1);
        float h1v = (1.0f - z1) * c1;

        *(float2*)&g_h1[(size_t)row * G1U + j] = make_float2(h0, h1v);
    }
}

// =====================================================================
// Kernel 2: h2 = GRU2(h1, h=0).  GEMM [65536,384] x [384,48] fused gates.
// Block: 128 rows x all 16 units (48 cols). tx = unit j, ty -> 8 rows.
// =====================================================================
__global__ __launch_bounds__(256, 2)
void gemm2_kernel(const float* __restrict__ W, const float* __restrict__ bias)
{
    __shared__ float As[16][130];
    __shared__ float Bs[16][48];

    const int t  = threadIdx.x;
    const int tx = t & 15;
    const int ty = t >> 4;
    const int m0 = blockIdx.x * 128;

    float accz[8], accr[8], acch[8];
#pragma unroll
    for (int m = 0; m < 8; ++m) { accz[m] = 0.f; accr[m] = 0.f; acch[m] = 0.f; }

    for (int kt = 0; kt < 24; ++kt) {
        const int k0 = kt * 16;
        __syncthreads();
#pragma unroll
        for (int it = 0; it < 8; ++it) {
            int idx = t + it * 256;
            int m   = idx >> 4;
            int kk  = idx & 15;
            As[kk][m] = g_h1[(size_t)(m0 + m) * G1U + k0 + kk];
        }
#pragma unroll
        for (int it = 0; it < 3; ++it) {
            int idx = t + it * 256;   // 0..767
            int kk  = idx / 48;
            int c   = idx % 48;
            Bs[kk][c] = W[(size_t)(k0 + kk) * 48 + c];
        }
        __syncthreads();
#pragma unroll
        for (int k = 0; k < 16; ++k) {
            const float bz = Bs[k][tx];
            const float br = Bs[k][16 + tx];
            const float bh = Bs[k][32 + tx];
#pragma unroll
            for (int m = 0; m < 8; ++m) {
                const float a = As[k][ty * 8 + m];
                accz[m] = fmaf(a, bz, accz[m]);
                accr[m] = fmaf(a, br, accr[m]);
                acch[m] = fmaf(a, bh, acch[m]);
            }
        }
    }

    const float b0z = bias[tx],      b0r = bias[16 + tx],      b0h = bias[32 + tx];
    const float b1z = bias[48 + tx], b1r = bias[64 + tx],      b1h = bias[80 + tx];
#pragma unroll
    for (int m = 0; m < 8; ++m) {
        const int row = m0 + ty * 8 + m;
        float z  = sigmoid_f(accz[m] + b0z + b1z);
        float r  = sigmoid_f(accr[m] + b0r + b1r);
        float hc = tanhf(acch[m] + b0h + r * b1h);
        g_h2[(size_t)row * G2U + tx] = (1.0f - z) * hc;
    }
}

// =====================================================================
// Kernel 3: d = g1*tanh(h2@W1+b1) + g2*tanh(h2@W2+b2); softmax.
// One warp per row group (8 rows, processed 2 at a time). Lane q-levels:
// lane handles levels l = lane + 32*q, q=0..7. Warp-shfl softmax.
// =====================================================================
__global__ __launch_bounds__(256)
void head_kernel(const float* __restrict__ w1, const float* __restrict__ b1,
                 const float* __restrict__ w2, const float* __restrict__ b2,
                 const float* __restrict__ gv1, const float* __restrict__ gv2,
                 float* __restrict__ out)
{
    __shared__ float W1s[16 * NLEV];
    __shared__ float W2s[16 * NLEV];
    __shared__ float b1s[NLEV], b2s[NLEV], g1s[NLEV], g2s[NLEV];

    const int t = threadIdx.x;
    for (int i = t; i < 16 * NLEV; i += 256) { W1s[i] = w1[i]; W2s[i] = w2[i]; }
    b1s[t] = b1[t]; b2s[t] = b2[t]; g1s[t] = gv1[t]; g2s[t] = gv2[t];
    __syncthreads();

    const int warp = t >> 5, lane = t & 31;
    const int gwarp = blockIdx.x * 8 + warp;     // 8192 warps total

    for (int p = 0; p < 4; ++p) {
        const int r0 = gwarp * 8 + p * 2;        // two rows: r0, r0+1
        // broadcast-load the two h2 rows (L1 serves identical addresses)
        float ha[16], hb[16];
        {
            const float4* pa = (const float4*)&g_h2[(size_t)r0 * G2U];
            const float4* pb = (const float4*)&g_h2[(size_t)(r0 + 1) * G2U];
#pragma unroll
            for (int i = 0; i < 4; ++i) {
                float4 va = __ldg(pa + i);
                float4 vb = __ldg(pb + i);
                ha[4*i] = va.x; ha[4*i+1] = va.y; ha[4*i+2] = va.z; ha[4*i+3] = va.w;
                hb[4*i] = vb.x; hb[4*i+1] = vb.y; hb[4*i+2] = vb.z; hb[4*i+3] = vb.w;
            }
        }
        float a1a[8], a2a[8], a1b[8], a2b[8];
#pragma unroll
        for (int q = 0; q < 8; ++q) { a1a[q]=0.f; a2a[q]=0.f; a1b[q]=0.f; a2b[q]=0.f; }
#pragma unroll
        for (int k = 0; k < 16; ++k) {
            const float hka = ha[k], hkb = hb[k];
#pragma unroll
            for (int q = 0; q < 8; ++q) {
                const int l = lane + 32 * q;
                const float wv1 = W1s[k * NLEV + l];
                const float wv2 = W2s[k * NLEV + l];
                a1a[q] = fmaf(hka, wv1, a1a[q]);
                a2a[q] = fmaf(hka, wv2, a2a[q]);
                a1b[q] = fmaf(hkb, wv1, a1b[q]);
                a2b[q] = fmaf(hkb, wv2, a2b[q]);
            }
        }
        // per-row epilogue: gated tanh + softmax
#pragma unroll
        for (int ri = 0; ri < 2; ++ri) {
            float v[8];
#pragma unroll
            for (int q = 0; q < 8; ++q) {
                const int l = lane + 32 * q;
                const float t1 = tanhf((ri ? a1b[q] : a1a[q]) + b1s[l]);
                const float t2 = tanhf((ri ? a2b[q] : a2a[q]) + b2s[l]);
                v[q] = g1s[l] * t1 + g2s[l] * t2;
            }
            float mx = v[0];
#pragma unroll
            for (int q = 1; q < 8; ++q) mx = fmaxf(mx, v[q]);
#pragma unroll
            for (int off = 16; off >= 1; off >>= 1)
                mx = fmaxf(mx, __shfl_xor_sync(0xffffffffu, mx, off));
            float e[8], s = 0.f;
#pragma unroll
            for (int q = 0; q < 8; ++q) { e[q] = __expf(v[q] - mx); s += e[q]; }
#pragma unroll
            for (int off = 16; off >= 1; off >>= 1)
                s += __shfl_xor_sync(0xffffffffu, s, off);
            const float inv = 1.0f / s;
            float* orow = out + (size_t)(r0 + ri) * NLEV;
#pragma unroll
            for (int q = 0; q < 8; ++q)
                orow[lane + 32 * q] = e[q] * inv;
        }
    }
}

// =====================================================================
extern "C" void kernel_launch(void* const* d_in, const int* in_sizes, int n_in,
                              void* d_out, int out_size)
{
    const float* x1   = (const float*)d_in[0];
    const float* x2   = (const float*)d_in[1];
    const float* g1k  = (const float*)d_in[2];
    // d_in[3] = gru1_rkernel: unused (h=0 -> only recurrent bias matters)
    const float* g1b  = (const float*)d_in[4];
    const float* g2k  = (const float*)d_in[5];
    // d_in[6] = gru2_rkernel: unused
    const float* g2b  = (const float*)d_in[7];
    const float* fw1  = (const float*)d_in[8];
    const float* fb1  = (const float*)d_in[9];
    const float* fw2  = (const float*)d_in[10];
    const float* fb2  = (const float*)d_in[11];
    const float* fg1  = (const float*)d_in[12];
    const float* fg2  = (const float*)d_in[13];
    float* out = (float*)d_out;

    dim3 grid1(G1U / 32, NB / 128);            // 12 x 512 (j-blocks fastest: L2 row reuse)
    gemm1_kernel<<<grid1, 256>>>(x1, x2, g1k, g1b);
    gemm2_kernel<<<NB / 128, 256>>>(g2k, g2b);
    head_kernel<<<NB / 64, 256>>>(fw1, fb1, fw2, fb2, fg1, fg2, out);
}

// round 3
// speedup vs baseline: 2.7843x; 2.7843x over previous
#include <cuda_runtime.h>
#include <cuda_bf16.h>
#include <cstdint>

// ---------------- problem constants ----------------
#define NB     65536
#define IN1    384
#define IN2    128
#define KDIM   512
#define G1U    384
#define N1     1152
#define G2U    16
#define NLEV   256

typedef unsigned long long u64;
typedef unsigned int u32;

// ---------------- device scratch ----------------
__device__ __nv_bfloat16 g_Ahi[(size_t)NB * KDIM];    // 64 MB
__device__ __nv_bfloat16 g_Alo[(size_t)NB * KDIM];    // 64 MB
__device__ __nv_bfloat16 g_Bhi[(size_t)N1 * KDIM];    // reordered+transposed W
__device__ __nv_bfloat16 g_Blo[(size_t)N1 * KDIM];
__device__ float g_h1[(size_t)NB * G1U];              // 96 MB
__device__ float g_h2[(size_t)NB * G2U];              // 4 MB

// ---------------- helpers ----------------
__device__ __forceinline__ u32 smem_u32(const void* p) {
    u32 a;
    asm("{ .reg .u64 t; cvta.to.shared.u64 t, %1; cvt.u32.u64 %0, t; }" : "=r"(a) : "l"(p));
    return a;
}
__device__ __forceinline__ u32 swz(u32 x) { return x ^ ((x >> 3) & 0x70); }

#define CP_ASYNC16(dst, src) \
    asm volatile("cp.async.cg.shared.global [%0], [%1], 16;" :: "r"(dst), "l"(src) : "memory")
#define CP_COMMIT() asm volatile("cp.async.commit_group;" ::: "memory")
#define CP_WAIT2()  asm volatile("cp.async.wait_group 2;" ::: "memory")

#define LDSM_X4(r0, r1, r2, r3, addr) \
    asm volatile("ldmatrix.sync.aligned.m8n8.x4.shared.b16 {%0,%1,%2,%3}, [%4];" \
        : "=r"(r0), "=r"(r1), "=r"(r2), "=r"(r3) : "r"(addr))

#define MMA16816(d, a, b) \
    asm volatile("mma.sync.aligned.m16n8k16.row.col.f32.bf16.bf16.f32 " \
        "{%0,%1,%2,%3},{%4,%5,%6,%7},{%8,%9},{%0,%1,%2,%3};" \
        : "+f"((d)[0]), "+f"((d)[1]), "+f"((d)[2]), "+f"((d)[3]) \
        : "r"((a)[0]), "r"((a)[1]), "r"((a)[2]), "r"((a)[3]), "r"((b)[0]), "r"((b)[1]))

__device__ __forceinline__ float sigmoid_f(float x) {
    return __fdividef(1.0f, 1.0f + __expf(-x));
}
__device__ __forceinline__ float tanh_f(float x) {
    return __fdividef(2.0f, 1.0f + __expf(-2.0f * x)) - 1.0f;
}

// =====================================================================
// Prep 1: split A = concat(x1,x2) into hi/lo bf16
// =====================================================================
__global__ __launch_bounds__(256)
void conv_a_kernel(const float* __restrict__ x1, const float* __restrict__ x2)
{
    size_t i4 = (size_t)blockIdx.x * 256 + threadIdx.x;   // 8388608 chunks of 4
    int m  = (int)(i4 >> 7);
    int c4 = ((int)i4 & 127) * 4;
    float4 v;
    if (c4 < IN1) v = *(const float4*)(x1 + (size_t)m * IN1 + c4);
    else          v = *(const float4*)(x2 + (size_t)m * IN2 + (c4 - IN1));
    float vv[4] = {v.x, v.y, v.z, v.w};
    __nv_bfloat16 hi[4], lo[4];
#pragma unroll
    for (int e = 0; e < 4; ++e) {
        hi[e] = __float2bfloat16(vv[e]);
        lo[e] = __float2bfloat16(vv[e] - __bfloat162float(hi[e]));
    }
    size_t o = (size_t)m * KDIM + c4;
    *(__nv_bfloat162*)&g_Ahi[o]     = __nv_bfloat162(hi[0], hi[1]);
    *(__nv_bfloat162*)&g_Ahi[o + 2] = __nv_bfloat162(hi[2], hi[3]);
    *(__nv_bfloat162*)&g_Alo[o]     = __nv_bfloat162(lo[0], lo[1]);
    *(__nv_bfloat162*)&g_Alo[o + 2] = __nv_bfloat162(lo[2], lo[3]);
}

// =====================================================================
// Prep 2: W [512,1152] -> transposed bf16 hi/lo, layout:
// unit j, gate g -> n' = (j/16)*48 + g*16 + (j%16);  B'[n'][k]
// =====================================================================
__global__ __launch_bounds__(256)
void conv_w_kernel(const float* __restrict__ W)
{
    int idx = blockIdx.x * 256 + threadIdx.x;   // < 589824
    int k = idx / N1, c = idx % N1;
    int g = c / G1U, j = c % G1U;
    int n = (j >> 4) * 48 + g * 16 + (j & 15);
    float v = W[idx];
    __nv_bfloat16 hi = __float2bfloat16(v);
    __nv_bfloat16 lo = __float2bfloat16(v - __bfloat162float(hi));
    g_Bhi[(size_t)n * KDIM + k] = hi;
    g_Blo[(size_t)n * KDIM + k] = lo;
}

// =====================================================================
// GEMM1 via mma.sync bf16x3: h1 = GRU1(A, h=0).
// CTA tile M=128 x N=96 (= 2 groups of 16 units x 3 gates).
// 8 warps: warp tile 32x48.  K pipeline: 24 tiles of 64 (3 passes x 8).
// 3-stage cp.async double... triple buffer.
// =====================================================================
#define KT1       64
#define STAGE_B   28672            // 16KB A + 12KB B
#define OFF_B     16384
#define NSTG      3
#define BIAS_OFF  (NSTG * STAGE_B) // 86016
#define SMEM_TOT  (BIAS_OFF + 512)

__device__ __forceinline__ void load_stage_g1(u32 sb, int s, int kt, int m0, int nb, int tid)
{
    // pass p: 0 = Ahi*Bhi, 1 = Ahi*Blo, 2 = Alo*Bhi
    const int p   = kt >> 3;
    const int k0  = (kt & 7) * KT1;
    const char* Ap = (const char*)(p == 2 ? g_Alo : g_Ahi);
    const char* Bp = (const char*)(p == 1 ? g_Blo : g_Bhi);
    const u32 base = sb + s * STAGE_B;
    // A tile: 128 rows x 128B
#pragma unroll
    for (int i = 0; i < 4; ++i) {
        int c = tid + i * 256;              // 0..1023
        int row = c >> 3, cb = c & 7;
        u32 dst = base + swz(row * 128 + cb * 16);
        const char* src = Ap + (size_t)(m0 + row) * (KDIM * 2) + k0 * 2 + cb * 16;
        CP_ASYNC16(dst, src);
    }
    // B tile: 96 rows x 128B
#pragma unroll
    for (int i = 0; i < 3; ++i) {
        int c = tid + i * 256;              // 0..767
        int row = c >> 3, cb = c & 7;
        u32 dst = base + OFF_B + swz(row * 128 + cb * 16);
        const char* src = Bp + (size_t)(nb * 96 + row) * (KDIM * 2) + k0 * 2 + cb * 16;
        CP_ASYNC16(dst, src);
    }
}

__global__ __launch_bounds__(256, 2)
void gemm1_mma_kernel(const float* __restrict__ bias)
{
    extern __shared__ char smem[];
    const u32 sb = smem_u32(smem);
    const int tid  = threadIdx.x;
    const int warp = tid >> 5, lane = tid & 31;
    const int wm = warp & 3;          // m block: 32*wm
    const int wn = warp >> 2;         // n block: 48*wn
    const int nb = blockIdx.x;        // 0..11  (32-unit block)
    const int m0 = blockIdx.y * 128;  // 0..511

    // stage combined biases (32 units for this CTA)
    float* czs  = (float*)(smem + BIAS_OFF);
    float* crs  = czs + 32;
    float* ch0s = czs + 64;
    float* ch1s = czs + 96;
    if (tid < 32) {
        int j = nb * 32 + tid;
        czs[tid]  = bias[j]         + bias[N1 + j];
        crs[tid]  = bias[G1U + j]   + bias[N1 + G1U + j];
        ch0s[tid] = bias[2 * G1U + j];
        ch1s[tid] = bias[N1 + 2 * G1U + j];
    }

    float acc[2][6][4];
#pragma unroll
    for (int mi = 0; mi < 2; ++mi)
#pragma unroll
        for (int ni = 0; ni < 6; ++ni)
#pragma unroll
            for (int e = 0; e < 4; ++e) acc[mi][ni][e] = 0.f;

    // precompute per-lane ldmatrix address components
    const int a_row = 32 * wm + (lane & 15);
    const int a_kb  = (lane & 16) ? 16 : 0;
    const int b_row = 48 * wn + (lane & 7) + ((lane & 16) ? 8 : 0);
    const int b_kb  = (lane & 8) ? 16 : 0;

    // prologue: fill stages 0,1
    load_stage_g1(sb, 0, 0, m0, nb, tid); CP_COMMIT();
    load_stage_g1(sb, 1, 1, m0, nb, tid); CP_COMMIT();

    for (int kt = 0; kt < 24; ++kt) {
        const int s = kt % NSTG;
        if (kt + 2 < 24) load_stage_g1(sb, (kt + 2) % NSTG, kt + 2, m0, nb, tid);
        CP_COMMIT();
        CP_WAIT2();
        __syncthreads();

        const u32 abase = sb + s * STAGE_B;
        const u32 bbase = abase + OFF_B;
#pragma unroll
        for (int ks = 0; ks < 4; ++ks) {
            u32 af[2][4], bf[3][4];
#pragma unroll
            for (int mi = 0; mi < 2; ++mi) {
                u32 ad = abase + swz((u32)(a_row + mi * 16) * 128 + ks * 32 + a_kb);
                LDSM_X4(af[mi][0], af[mi][1], af[mi][2], af[mi][3], ad);
            }
#pragma unroll
            for (int bi = 0; bi < 3; ++bi) {
                u32 bd = bbase + swz((u32)(b_row + bi * 16) * 128 + ks * 32 + b_kb);
                LDSM_X4(bf[bi][0], bf[bi][1], bf[bi][2], bf[bi][3], bd);
            }
#pragma unroll
            for (int mi = 0; mi < 2; ++mi)
#pragma unroll
                for (int bi = 0; bi < 3; ++bi) {
                    MMA16816(acc[mi][2 * bi],     af[mi], (&bf[bi][0]));
                    MMA16816(acc[mi][2 * bi + 1], af[mi], (&bf[bi][2]));
                }
        }
        __syncthreads();
    }

    // ---- fused GRU epilogue: z=acc[.][ni], r=acc[.][ni+2], h=acc[.][ni+4]
    const int qr = lane >> 2, qc = lane & 3;
#pragma unroll
    for (int mi = 0; mi < 2; ++mi) {
#pragma unroll
        for (int nip = 0; nip < 2; ++nip) {
            const int u0 = 8 * nip + 2 * qc;          // unit (0..31 within 16-grp x ...)
            // NOTE: warp wn selects 16-unit group; u0 in 0..15 range? u0 = 8*nip+2*qc <= 14 ✓
            const int j0 = nb * 32 + wn * 16 + u0;    // global unit of element e=0
            const float cz0 = czs[wn * 16 + u0],     cz1 = czs[wn * 16 + u0 + 1];
            const float cr0 = crs[wn * 16 + u0],     cr1 = crs[wn * 16 + u0 + 1];
            const float c00 = ch0s[wn * 16 + u0],    c01 = ch0s[wn * 16 + u0 + 1];
            const float c10 = ch1s[wn * 16 + u0],    c11 = ch1s[wn * 16 + u0 + 1];
            const float* az = acc[mi][nip];
            const float* ar = acc[mi][nip + 2];
            const float* ah = acc[mi][nip + 4];
#pragma unroll
            for (int half = 0; half < 2; ++half) {   // d0,d1 (row r) / d2,d3 (row r+8)
                const int row = m0 + 32 * wm + mi * 16 + qr + half * 8;
                float z0 = sigmoid_f(az[2 * half]     + cz0);
                float z1 = sigmoid_f(az[2 * half + 1] + cz1);
                float r0 = sigmoid_f(ar[2 * half]     + cr0);
                float r1 = sigmoid_f(ar[2 * half + 1] + cr1);
                float h0 = tanh_f(ah[2 * half]     + c00 + r0 * c10);
                float h1 = tanh_f(ah[2 * half + 1] + c01 + r1 * c11);
                float2 o = make_float2((1.f - z0) * h0, (1.f - z1) * h1);
                *(float2*)&g_h1[(size_t)row * G1U + j0] = o;
            }
        }
    }
}

// =====================================================================
// Kernel 2: h2 = GRU2(h1, h=0). SIMT (small: 2.4 GFLOP).
// =====================================================================
__global__ __launch_bounds__(256, 2)
void gemm2_kernel(const float* __restrict__ W, const float* __restrict__ bias)
{
    __shared__ float As[16][130];
    __shared__ float Bs[16][48];

    const int t  = threadIdx.x;
    const int tx = t & 15;
    const int ty = t >> 4;
    const int m0 = blockIdx.x * 128;

    float accz[8], accr[8], acch[8];
#pragma unroll
    for (int m = 0; m < 8; ++m) { accz[m] = 0.f; accr[m] = 0.f; acch[m] = 0.f; }

    for (int kt = 0; kt < 24; ++kt) {
        const int k0 = kt * 16;
        __syncthreads();
#pragma unroll
        for (int it = 0; it < 8; ++it) {
            int idx = t + it * 256;
            int m   = idx >> 4;
            int kk  = idx & 15;
            As[kk][m] = g_h1[(size_t)(m0 + m) * G1U + k0 + kk];
        }
#pragma unroll
        for (int it = 0; it < 3; ++it) {
            int idx = t + it * 256;
            int kk  = idx / 48;
            int c   = idx % 48;
            Bs[kk][c] = W[(size_t)(k0 + kk) * 48 + c];
        }
        __syncthreads();
#pragma unroll
        for (int k = 0; k < 16; ++k) {
            const float bz = Bs[k][tx];
            const float br = Bs[k][16 + tx];
            const float bh = Bs[k][32 + tx];
#pragma unroll
            for (int m = 0; m < 8; ++m) {
                const float a = As[k][ty * 8 + m];
                accz[m] = fmaf(a, bz, accz[m]);
                accr[m] = fmaf(a, br, accr[m]);
                acch[m] = fmaf(a, bh, acch[m]);
            }
        }
    }

    const float b0z = bias[tx],      b0r = bias[16 + tx], b0h = bias[32 + tx];
    const float b1z = bias[48 + tx], b1r = bias[64 + tx], b1h = bias[80 + tx];
#pragma unroll
    for (int m = 0; m < 8; ++m) {
        const int row = m0 + ty * 8 + m;
        float z  = sigmoid_f(accz[m] + b0z + b1z);
        float r  = sigmoid_f(accr[m] + b0r + b1r);
        float hc = tanh_f(acch[m] + b0h + r * b1h);
        g_h2[(size_t)row * G2U + tx] = (1.0f - z) * hc;
    }
}

// =====================================================================
// Kernel 3: head + softmax. One warp per 8 rows (2 at a time).
// =====================================================================
__global__ __launch_bounds__(256)
void head_kernel(const float* __restrict__ w1, const float* __restrict__ b1,
                 const float* __restrict__ w2, const float* __restrict__ b2,
                 const float* __restrict__ gv1, const float* __restrict__ gv2,
                 float* __restrict__ out)
{
    __shared__ float W1s[16 * NLEV];
    __shared__ float W2s[16 * NLEV];
    __shared__ float b1s[NLEV], b2s[NLEV], g1s[NLEV], g2s[NLEV];

    const int t = threadIdx.x;
    for (int i = t; i < 16 * NLEV; i += 256) { W1s[i] = w1[i]; W2s[i] = w2[i]; }
    b1s[t] = b1[t]; b2s[t] = b2[t]; g1s[t] = gv1[t]; g2s[t] = gv2[t];
    __syncthreads();

    const int warp = t >> 5, lane = t & 31;
    const int gwarp = blockIdx.x * 8 + warp;

    for (int p = 0; p < 4; ++p) {
        const int r0 = gwarp * 8 + p * 2;
        float ha[16], hb[16];
        {
            const float4* pa = (const float4*)&g_h2[(size_t)r0 * G2U];
            const float4* pb = (const float4*)&g_h2[(size_t)(r0 + 1) * G2U];
#pragma unroll
            for (int i = 0; i < 4; ++i) {
                float4 va = __ldg(pa + i);
                float4 vb = __ldg(pb + i);
                ha[4*i] = va.x; ha[4*i+1] = va.y; ha[4*i+2] = va.z; ha[4*i+3] = va.w;
                hb[4*i] = vb.x; hb[4*i+1] = vb.y; hb[4*i+2] = vb.z; hb[4*i+3] = vb.w;
            }
        }
        float a1a[8], a2a[8], a1b[8], a2b[8];
#pragma unroll
        for (int q = 0; q < 8; ++q) { a1a[q]=0.f; a2a[q]=0.f; a1b[q]=0.f; a2b[q]=0.f; }
#pragma unroll
        for (int k = 0; k < 16; ++k) {
            const float hka = ha[k], hkb = hb[k];
#pragma unroll
            for (int q = 0; q < 8; ++q) {
                const int l = lane + 32 * q;
                const float wv1 = W1s[k * NLEV + l];
                const float wv2 = W2s[k * NLEV + l];
                a1a[q] = fmaf(hka, wv1, a1a[q]);
                a2a[q] = fmaf(hka, wv2, a2a[q]);
                a1b[q] = fmaf(hkb, wv1, a1b[q]);
                a2b[q] = fmaf(hkb, wv2, a2b[q]);
            }
        }
#pragma unroll
        for (int ri = 0; ri < 2; ++ri) {
            float v[8];
#pragma unroll
            for (int q = 0; q < 8; ++q) {
                const int l = lane + 32 * q;
                const float t1 = tanh_f((ri ? a1b[q] : a1a[q]) + b1s[l]);
                const float t2 = tanh_f((ri ? a2b[q] : a2a[q]) + b2s[l]);
                v[q] = g1s[l] * t1 + g2s[l] * t2;
            }
            float mx = v[0];
#pragma unroll
            for (int q = 1; q < 8; ++q) mx = fmaxf(mx, v[q]);
#pragma unroll
            for (int off = 16; off >= 1; off >>= 1)
                mx = fmaxf(mx, __shfl_xor_sync(0xffffffffu, mx, off));
            float e[8], s = 0.f;
#pragma unroll
            for (int q = 0; q < 8; ++q) { e[q] = __expf(v[q] - mx); s += e[q]; }
#pragma unroll
            for (int off = 16; off >= 1; off >>= 1)
                s += __shfl_xor_sync(0xffffffffu, s, off);
            const float inv = 1.0f / s;
            float* orow = out + (size_t)(r0 + ri) * NLEV;
#pragma unroll
            for (int q = 0; q < 8; ++q)
                orow[lane + 32 * q] = e[q] * inv;
        }
    }
}

// =====================================================================
extern "C" void kernel_launch(void* const* d_in, const int* in_sizes, int n_in,
                              void* d_out, int out_size)
{
    const float* x1   = (const float*)d_in[0];
    const float* x2   = (const float*)d_in[1];
    const float* g1k  = (const float*)d_in[2];
    const float* g1b  = (const float*)d_in[4];
    const float* g2k  = (const float*)d_in[5];
    const float* g2b  = (const float*)d_in[7];
    const float* fw1  = (const float*)d_in[8];
    const float* fb1  = (const float*)d_in[9];
    const float* fw2  = (const float*)d_in[10];
    const float* fb2  = (const float*)d_in[11];
    const float* fg1  = (const float*)d_in[12];
    const float* fg2  = (const float*)d_in[13];
    float* out = (float*)d_out;

    cudaFuncSetAttribute(gemm1_mma_kernel,
                         cudaFuncAttributeMaxDynamicSharedMemorySize, SMEM_TOT);

    conv_a_kernel<<<(NB * (KDIM / 4)) / 256, 256>>>(x1, x2);
    conv_w_kernel<<<(KDIM * N1) / 256, 256>>>(g1k);
    gemm1_mma_kernel<<<dim3(12, NB / 128), 256, SMEM_TOT>>>(g1b);
    gemm2_kernel<<<NB / 128, 256>>>(g2k, g2b);
    head_kernel<<<NB / 64, 256>>>(fw1, fb1, fw2, fb2, fg1, fg2, out);
}

// round 4
// speedup vs baseline: 5.6367x; 2.0245x over previous
#include <cuda_runtime.h>
#include <cuda_fp16.h>
#include <cstdint>

// ---------------- problem constants ----------------
#define NB     65536
#define IN1    384
#define IN2    128
#define KDIM   512
#define G1U    384
#define N1     1152
#define G2U    16
#define NLEV   256

typedef unsigned long long u64;
typedef unsigned int u32;

// ---------------- device scratch ----------------
__device__ __half g_Ah[(size_t)NB * KDIM];     // 64 MB  fp16 concat(x1,x2)
__device__ __half g_Bh[(size_t)N1 * KDIM];     // reordered+transposed W1
__device__ __half g_h1h[(size_t)NB * G1U];     // 48 MB  fp16 h1
__device__ __half g_B2[(size_t)48 * G1U];      // transposed W2
__device__ float  g_h2[(size_t)NB * G2U];      // 4 MB   fp32 h2

// ---------------- helpers ----------------
__device__ __forceinline__ u32 smem_u32(const void* p) {
    u32 a;
    asm("{ .reg .u64 t; cvta.to.shared.u64 t, %1; cvt.u32.u64 %0, t; }" : "=r"(a) : "l"(p));
    return a;
}
__device__ __forceinline__ u32 swz(u32 x) { return x ^ ((x >> 3) & 0x70); }

#define CP_ASYNC16(dst, src) \
    asm volatile("cp.async.cg.shared.global [%0], [%1], 16;" :: "r"(dst), "l"(src) : "memory")
#define CP_COMMIT() asm volatile("cp.async.commit_group;" ::: "memory")
#define CP_WAIT3()  asm volatile("cp.async.wait_group 3;" ::: "memory")
#define CP_WAIT2()  asm volatile("cp.async.wait_group 2;" ::: "memory")

#define LDSM_X4(r0, r1, r2, r3, addr) \
    asm volatile("ldmatrix.sync.aligned.m8n8.x4.shared.b16 {%0,%1,%2,%3}, [%4];" \
        : "=r"(r0), "=r"(r1), "=r"(r2), "=r"(r3) : "r"(addr))

#define MMA16816(d, a, b) \
    asm volatile("mma.sync.aligned.m16n8k16.row.col.f32.f16.f16.f32 " \
        "{%0,%1,%2,%3},{%4,%5,%6,%7},{%8,%9},{%0,%1,%2,%3};" \
        : "+f"((d)[0]), "+f"((d)[1]), "+f"((d)[2]), "+f"((d)[3]) \
        : "r"((a)[0]), "r"((a)[1]), "r"((a)[2]), "r"((a)[3]), "r"((b)[0]), "r"((b)[1]))

__device__ __forceinline__ float sigmoid_f(float x) {
    return __fdividef(1.0f, 1.0f + __expf(-x));
}
__device__ __forceinline__ float tanh_f(float x) {
    return __fdividef(2.0f, 1.0f + __expf(-2.0f * x)) - 1.0f;
}

// =====================================================================
// Prep 1: A = concat(x1,x2) -> fp16
// =====================================================================
__global__ __launch_bounds__(256)
void conv_a_kernel(const float* __restrict__ x1, const float* __restrict__ x2)
{
    size_t i4 = (size_t)blockIdx.x * 256 + threadIdx.x;   // 8388608 chunks of 4
    int m  = (int)(i4 >> 7);
    int c4 = ((int)i4 & 127) * 4;
    float4 v;
    if (c4 < IN1) v = *(const float4*)(x1 + (size_t)m * IN1 + c4);
    else          v = *(const float4*)(x2 + (size_t)m * IN2 + (c4 - IN1));
    size_t o = (size_t)m * KDIM + c4;
    *(__half2*)&g_Ah[o]     = __floats2half2_rn(v.x, v.y);
    *(__half2*)&g_Ah[o + 2] = __floats2half2_rn(v.z, v.w);
}

// =====================================================================
// Prep 2: W1 [512,1152] -> transposed fp16, layout n' = (j/16)*48 + g*16 + j%16
// =====================================================================
__global__ __launch_bounds__(256)
void conv_w1_kernel(const float* __restrict__ W)
{
    int idx = blockIdx.x * 256 + threadIdx.x;   // < 589824
    int k = idx / N1, c = idx % N1;
    int g = c / G1U, j = c % G1U;
    int n = (j >> 4) * 48 + g * 16 + (j & 15);
    g_Bh[(size_t)n * KDIM + k] = __float2half_rn(W[idx]);
}

// =====================================================================
// Prep 3: W2 [384,48] -> transposed fp16  (col c = g*16+u already gate-grouped)
// =====================================================================
__global__ __launch_bounds__(256)
void conv_w2_kernel(const float* __restrict__ W)
{
    int idx = blockIdx.x * 256 + threadIdx.x;   // < 18432
    if (idx >= G1U * 48) return;
    int k = idx / 48, c = idx % 48;
    g_B2[(size_t)c * G1U + k] = __float2half_rn(W[idx]);
}

// =====================================================================
// GEMM1: h1 = GRU1(A, h=0).  fp16 single-pass HMMA.
// CTA tile 256 x 96 (= 2 groups of 16 units x 3 gates); 8 warps of 64x48.
// K = 512 -> 8 tiles of 64; 4-stage cp.async pipeline.
// =====================================================================
#define G1_STAGE  45056          // 32KB A + 12KB B (padded 1KB)
#define G1_OFFB   32768
#define G1_BIAS   (4 * G1_STAGE) // 180224
#define G1_SMEM   (G1_BIAS + 512)

__device__ __forceinline__ void load_stage_g1(u32 sb, int s, int kt, int m0, int nb, int tid)
{
    const int k0 = kt * 64;
    const u32 base = sb + s * G1_STAGE;
    const char* Ap = (const char*)g_Ah;
    const char* Bp = (const char*)g_Bh;
    // A tile: 256 rows x 128B
#pragma unroll
    for (int i = 0; i < 8; ++i) {
        int c = tid + i * 256;              // 0..2047
        int row = c >> 3, cb = c & 7;
        u32 dst = base + swz(row * 128 + cb * 16);
        const char* src = Ap + (size_t)(m0 + row) * (KDIM * 2) + k0 * 2 + cb * 16;
        CP_ASYNC16(dst, src);
    }
    // B tile: 96 rows x 128B
#pragma unroll
    for (int i = 0; i < 3; ++i) {
        int c = tid + i * 256;              // 0..767
        int row = c >> 3, cb = c & 7;
        u32 dst = base + G1_OFFB + swz(row * 128 + cb * 16);
        const char* src = Bp + (size_t)(nb * 96 + row) * (KDIM * 2) + k0 * 2 + cb * 16;
        CP_ASYNC16(dst, src);
    }
}

__global__ __launch_bounds__(256, 1)
void gemm1_mma_kernel(const float* __restrict__ bias)
{
    extern __shared__ char smem[];
    const u32 sb = smem_u32(smem);
    const int tid  = threadIdx.x;
    const int warp = tid >> 5, lane = tid & 31;
    const int wm = warp >> 1;         // 0..3 : m block 64*wm
    const int wn = warp & 1;          // 0..1 : n block 48*wn
    const int nb = blockIdx.x;        // 0..11  (32-unit block)
    const int m0 = blockIdx.y * 256;

    // stage combined biases (32 units for this CTA)
    float* czs  = (float*)(smem + G1_BIAS);
    float* crs  = czs + 32;
    float* ch0s = czs + 64;
    float* ch1s = czs + 96;
    if (tid < 32) {
        int j = nb * 32 + tid;
        czs[tid]  = bias[j]         + bias[N1 + j];
        crs[tid]  = bias[G1U + j]   + bias[N1 + G1U + j];
        ch0s[tid] = bias[2 * G1U + j];
        ch1s[tid] = bias[N1 + 2 * G1U + j];
    }

    float acc[4][6][4];
#pragma unroll
    for (int mi = 0; mi < 4; ++mi)
#pragma unroll
        for (int ni = 0; ni < 6; ++ni)
#pragma unroll
            for (int e = 0; e < 4; ++e) acc[mi][ni][e] = 0.f;

    const int a_row = 64 * wm + (lane & 15);
    const int a_kb  = (lane & 16) ? 16 : 0;
    const int b_row = 48 * wn + (lane & 7) + ((lane & 16) ? 8 : 0);
    const int b_kb  = (lane & 8) ? 16 : 0;

    // prologue: fill stages 0,1,2
    load_stage_g1(sb, 0, 0, m0, nb, tid); CP_COMMIT();
    load_stage_g1(sb, 1, 1, m0, nb, tid); CP_COMMIT();
    load_stage_g1(sb, 2, 2, m0, nb, tid); CP_COMMIT();

    for (int kt = 0; kt < 8; ++kt) {
        const int s = kt & 3;
        if (kt + 3 < 8) load_stage_g1(sb, (kt + 3) & 3, kt + 3, m0, nb, tid);
        CP_COMMIT();
        CP_WAIT3();
        __syncthreads();

        const u32 abase = sb + s * G1_STAGE;
        const u32 bbase = abase + G1_OFFB;
#pragma unroll
        for (int ks = 0; ks < 4; ++ks) {
            u32 af[4][4], bf[3][4];
#pragma unroll
            for (int mi = 0; mi < 4; ++mi) {
                u32 ad = abase + swz((u32)(a_row + mi * 16) * 128 + ks * 32 + a_kb);
                LDSM_X4(af[mi][0], af[mi][1], af[mi][2], af[mi][3], ad);
            }
#pragma unroll
            for (int bi = 0; bi < 3; ++bi) {
                u32 bd = bbase + swz((u32)(b_row + bi * 16) * 128 + ks * 32 + b_kb);
                LDSM_X4(bf[bi][0], bf[bi][1], bf[bi][2], bf[bi][3], bd);
            }
#pragma unroll
            for (int mi = 0; mi < 4; ++mi)
#pragma unroll
                for (int bi = 0; bi < 3; ++bi) {
                    MMA16816(acc[mi][2 * bi],     af[mi], (&bf[bi][0]));
                    MMA16816(acc[mi][2 * bi + 1], af[mi], (&bf[bi][2]));
                }
        }
        __syncthreads();
    }

    // ---- fused GRU epilogue: z=acc[.][nip], r=acc[.][nip+2], h=acc[.][nip+4]
    const int qr = lane >> 2, qc = lane & 3;
#pragma unroll
    for (int mi = 0; mi < 4; ++mi) {
#pragma unroll
        for (int nip = 0; nip < 2; ++nip) {
            const int ul = wn * 16 + 8 * nip + 2 * qc;   // 0..31
            const int j0 = nb * 32 + ul;
            const float cz0 = czs[ul],  cz1 = czs[ul + 1];
            const float cr0 = crs[ul],  cr1 = crs[ul + 1];
            const float c00 = ch0s[ul], c01 = ch0s[ul + 1];
            const float c10 = ch1s[ul], c11 = ch1s[ul + 1];
            const float* az = acc[mi][nip];
            const float* ar = acc[mi][nip + 2];
            const float* ah = acc[mi][nip + 4];
#pragma unroll
            for (int half = 0; half < 2; ++half) {
                const int row = m0 + 64 * wm + 16 * mi + qr + half * 8;
                float z0 = sigmoid_f(az[2 * half]     + cz0);
                float z1 = sigmoid_f(az[2 * half + 1] + cz1);
                float r0 = sigmoid_f(ar[2 * half]     + cr0);
                float r1 = sigmoid_f(ar[2 * half + 1] + cr1);
                float h0 = tanh_f(ah[2 * half]     + c00 + r0 * c10);
                float h1 = tanh_f(ah[2 * half + 1] + c01 + r1 * c11);
                *(__half2*)&g_h1h[(size_t)row * G1U + j0] =
                    __floats2half2_rn((1.f - z0) * h0, (1.f - z1) * h1);
            }
        }
    }
}

// =====================================================================
// GEMM2: h2 = GRU2(h1, h=0).  fp16 single-pass HMMA.
// CTA tile 128 x 48; 8 warps of 16x48. K = 384 -> 6 tiles; 3-stage pipeline.
// =====================================================================
#define G2_STAGE  22528          // 16KB A + 6KB B (padded)
#define G2_OFFB   16384
#define G2_BIAS   (3 * G2_STAGE) // 67584
#define G2_SMEM   (G2_BIAS + 512)

__device__ __forceinline__ void load_stage_g2(u32 sb, int s, int kt, int m0, int tid)
{
    const int k0 = kt * 64;
    const u32 base = sb + s * G2_STAGE;
    const char* Ap = (const char*)g_h1h;
    const char* Bp = (const char*)g_B2;
    // A tile: 128 rows x 128B
#pragma unroll
    for (int i = 0; i < 4; ++i) {
        int c = tid + i * 256;              // 0..1023
        int row = c >> 3, cb = c & 7;
        u32 dst = base + swz(row * 128 + cb * 16);
        const char* src = Ap + (size_t)(m0 + row) * (G1U * 2) + k0 * 2 + cb * 16;
        CP_ASYNC16(dst, src);
    }
    // B tile: 48 rows x 128B = 384 chunks
#pragma unroll
    for (int i = 0; i < 2; ++i) {
        int c = tid + i * 256;
        if (c < 384) {
            int row = c >> 3, cb = c & 7;
            u32 dst = base + G2_OFFB + swz(row * 128 + cb * 16);
            const char* src = Bp + (size_t)row * (G1U * 2) + k0 * 2 + cb * 16;
            CP_ASYNC16(dst, src);
        }
    }
}

__global__ __launch_bounds__(256, 2)
void gemm2_mma_kernel(const float* __restrict__ bias)
{
    extern __shared__ char smem[];
    const u32 sb = smem_u32(smem);
    const int tid  = threadIdx.x;
    const int warp = tid >> 5, lane = tid & 31;
    const int m0 = blockIdx.x * 128;

    float* czs  = (float*)(smem + G2_BIAS);
    float* crs  = czs + 16;
    float* ch0s = czs + 32;
    float* ch1s = czs + 48;
    if (tid < 16) {
        czs[tid]  = bias[tid]      + bias[48 + tid];
        crs[tid]  = bias[16 + tid] + bias[64 + tid];
        ch0s[tid] = bias[32 + tid];
        ch1s[tid] = bias[80 + tid];
    }

    float acc[6][4];
#pragma unroll
    for (int ni = 0; ni < 6; ++ni)
#pragma unroll
        for (int e = 0; e < 4; ++e) acc[ni][e] = 0.f;

    const int a_row = 16 * warp + (lane & 15);
    const int a_kb  = (lane & 16) ? 16 : 0;
    const int b_row = (lane & 7) + ((lane & 16) ? 8 : 0);
    const int b_kb  = (lane & 8) ? 16 : 0;

    load_stage_g2(sb, 0, 0, m0, tid); CP_COMMIT();
    load_stage_g2(sb, 1, 1, m0, tid); CP_COMMIT();

    for (int kt = 0; kt < 6; ++kt) {
        const int s = kt % 3;
        if (kt + 2 < 6) load_stage_g2(sb, (kt + 2) % 3, kt + 2, m0, tid);
        CP_COMMIT();
        CP_WAIT2();
        __syncthreads();

        const u32 abase = sb + s * G2_STAGE;
        const u32 bbase = abase + G2_OFFB;
#pragma unroll
        for (int ks = 0; ks < 4; ++ks) {
            u32 af[4], bf[3][4];
            u32 ad = abase + swz((u32)a_row * 128 + ks * 32 + a_kb);
            LDSM_X4(af[0], af[1], af[2], af[3], ad);
#pragma unroll
            for (int bi = 0; bi < 3; ++bi) {
                u32 bd = bbase + swz((u32)(b_row + bi * 16) * 128 + ks * 32 + b_kb);
                LDSM_X4(bf[bi][0], bf[bi][1], bf[bi][2], bf[bi][3], bd);
            }
#pragma unroll
            for (int bi = 0; bi < 3; ++bi) {
                MMA16816(acc[2 * bi],     af, (&bf[bi][0]));
                MMA16816(acc[2 * bi + 1], af, (&bf[bi][2]));
            }
        }
        __syncthreads();
    }

    // fused GRU epilogue
    const int qr = lane >> 2, qc = lane & 3;
#pragma unroll
    for (int nip = 0; nip < 2; ++nip) {
        const int u0 = 8 * nip + 2 * qc;
        const float cz0 = czs[u0],  cz1 = czs[u0 + 1];
        const float cr0 = crs[u0],  cr1 = crs[u0 + 1];
        const float c00 = ch0s[u0], c01 = ch0s[u0 + 1];
        const float c10 = ch1s[u0], c11 = ch1s[u0 + 1];
        const float* az = acc[nip];
        const float* ar = acc[nip + 2];
        const float* ah = acc[nip + 4];
#pragma unroll
        for (int half = 0; half < 2; ++half) {
            const int row = m0 + 16 * warp + qr + half * 8;
            float z0 = sigmoid_f(az[2 * half]     + cz0);
            float z1 = sigmoid_f(az[2 * half + 1] + cz1);
            float r0 = sigmoid_f(ar[2 * half]     + cr0);
            float r1 = sigmoid_f(ar[2 * half + 1] + cr1);
            float h0 = tanh_f(ah[2 * half]     + c00 + r0 * c10);
            float h1 = tanh_f(ah[2 * half + 1] + c01 + r1 * c11);
            *(float2*)&g_h2[(size_t)row * G2U + u0] =
                make_float2((1.f - z0) * h0, (1.f - z1) * h1);
        }
    }
}

// =====================================================================
// Kernel 3: head + softmax (fp32). One warp per 8 rows (2 at a time).
// =====================================================================
__global__ __launch_bounds__(256)
void head_kernel(const float* __restrict__ w1, const float* __restrict__ b1,
                 const float* __restrict__ w2, const float* __restrict__ b2,
                 const float* __restrict__ gv1, const float* __restrict__ gv2,
                 float* __restrict__ out)
{
    __shared__ float W1s[16 * NLEV];
    __shared__ float W2s[16 * NLEV];
    __shared__ float b1s[NLEV], b2s[NLEV], g1s[NLEV], g2s[NLEV];

    const int t = threadIdx.x;
    for (int i = t; i < 16 * NLEV; i += 256) { W1s[i] = w1[i]; W2s[i] = w2[i]; }
    b1s[t] = b1[t]; b2s[t] = b2[t]; g1s[t] = gv1[t]; g2s[t] = gv2[t];
    __syncthreads();

    const int warp = t >> 5, lane = t & 31;
    const int gwarp = blockIdx.x * 8 + warp;

    for (int p = 0; p < 4; ++p) {
        const int r0 = gwarp * 8 + p * 2;
        float ha[16], hb[16];
        {
            const float4* pa = (const float4*)&g_h2[(size_t)r0 * G2U];
            const float4* pb = (const float4*)&g_h2[(size_t)(r0 + 1) * G2U];
#pragma unroll
            for (int i = 0; i < 4; ++i) {
                float4 va = __ldg(pa + i);
                float4 vb = __ldg(pb + i);
                ha[4*i] = va.x; ha[4*i+1] = va.y; ha[4*i+2] = va.z; ha[4*i+3] = va.w;
                hb[4*i] = vb.x; hb[4*i+1] = vb.y; hb[4*i+2] = vb.z; hb[4*i+3] = vb.w;
            }
        }
        float a1a[8], a2a[8], a1b[8], a2b[8];
#pragma unroll
        for (int q = 0; q < 8; ++q) { a1a[q]=0.f; a2a[q]=0.f; a1b[q]=0.f; a2b[q]=0.f; }
#pragma unroll
        for (int k = 0; k < 16; ++k) {
            const float hka = ha[k], hkb = hb[k];
#pragma unroll
            for (int q = 0; q < 8; ++q) {
                const int l = lane + 32 * q;
                const float wv1 = W1s[k * NLEV + l];
                const float wv2 = W2s[k * NLEV + l];
                a1a[q] = fmaf(hka, wv1, a1a[q]);
                a2a[q] = fmaf(hka, wv2, a2a[q]);
                a1b[q] = fmaf(hkb, wv1, a1b[q]);
                a2b[q] = fmaf(hkb, wv2, a2b[q]);
            }
        }
#pragma unroll
        for (int ri = 0; ri < 2; ++ri) {
            float v[8];
#pragma unroll
            for (int q = 0; q < 8; ++q) {
                const int l = lane + 32 * q;
                const float t1 = tanh_f((ri ? a1b[q] : a1a[q]) + b1s[l]);
                const float t2 = tanh_f((ri ? a2b[q] : a2a[q]) + b2s[l]);
                v[q] = g1s[l] * t1 + g2s[l] * t2;
            }
            float mx = v[0];
#pragma unroll
            for (int q = 1; q < 8; ++q) mx = fmaxf(mx, v[q]);
#pragma unroll
            for (int off = 16; off >= 1; off >>= 1)
                mx = fmaxf(mx, __shfl_xor_sync(0xffffffffu, mx, off));
            float e[8], s = 0.f;
#pragma unroll
            for (int q = 0; q < 8; ++q) { e[q] = __expf(v[q] - mx); s += e[q]; }
#pragma unroll
            for (int off = 16; off >= 1; off >>= 1)
                s += __shfl_xor_sync(0xffffffffu, s, off);
            const float inv = 1.0f / s;
            float* orow = out + (size_t)(r0 + ri) * NLEV;
#pragma unroll
            for (int q = 0; q < 8; ++q)
                orow[lane + 32 * q] = e[q] * inv;
        }
    }
}

// =====================================================================
extern "C" void kernel_launch(void* const* d_in, const int* in_sizes, int n_in,
                              void* d_out, int out_size)
{
    const float* x1   = (const float*)d_in[0];
    const float* x2   = (const float*)d_in[1];
    const float* g1k  = (const float*)d_in[2];
    const float* g1b  = (const float*)d_in[4];
    const float* g2k  = (const float*)d_in[5];
    const float* g2b  = (const float*)d_in[7];
    const float* fw1  = (const float*)d_in[8];
    const float* fb1  = (const float*)d_in[9];
    const float* fw2  = (const float*)d_in[10];
    const float* fb2  = (const float*)d_in[11];
    const float* fg1  = (const float*)d_in[12];
    const float* fg2  = (const float*)d_in[13];
    float* out = (float*)d_out;

    cudaFuncSetAttribute(gemm1_mma_kernel,
                         cudaFuncAttributeMaxDynamicSharedMemorySize, G1_SMEM);
    cudaFuncSetAttribute(gemm2_mma_kernel,
                         cudaFuncAttributeMaxDynamicSharedMemorySize, G2_SMEM);

    conv_a_kernel<<<(NB * (KDIM / 4)) / 256, 256>>>(x1, x2);
    conv_w1_kernel<<<(KDIM * N1) / 256, 256>>>(g1k);
    conv_w2_kernel<<<(G1U * 48 + 255) / 256, 256>>>(g2k);
    gemm1_mma_kernel<<<dim3(12, NB / 256), 256, G1_SMEM>>>(g1b);
    gemm2_mma_kernel<<<NB / 128, 256, G2_SMEM>>>(g2b);
    head_kernel<<<NB / 64, 256>>>(fw1, fb1, fw2, fb2, fg1, fg2, out);
}

// round 5
// speedup vs baseline: 6.4123x; 1.1376x over previous
#include <cuda_runtime.h>
#include <cuda_fp16.h>
#include <cstdint>

// ---------------- problem constants ----------------
#define NB     65536
#define IN1    384
#define IN2    128
#define KDIM   512
#define G1U    384
#define N1     1152
#define G2U    16
#define NLEV   256

typedef unsigned long long u64;
typedef unsigned int u32;

// ---------------- device scratch ----------------
__device__ __half g_Ah[(size_t)NB * KDIM];     // 64 MB  fp16 concat(x1,x2)
__device__ __half g_Bh[(size_t)N1 * KDIM];     // reordered+transposed W1
__device__ __half g_h1h[(size_t)NB * G1U];     // 48 MB  fp16 h1
__device__ __half g_B2[(size_t)48 * G1U];      // transposed W2
__device__ float  g_h2[(size_t)NB * G2U];      // 4 MB   fp32 h2

// ---------------- helpers ----------------
__device__ __forceinline__ u32 smem_u32(const void* p) {
    u32 a;
    asm("{ .reg .u64 t; cvta.to.shared.u64 t, %1; cvt.u32.u64 %0, t; }" : "=r"(a) : "l"(p));
    return a;
}
__device__ __forceinline__ u32 swz(u32 x) { return x ^ ((x >> 3) & 0x70); }

#define CP_ASYNC16(dst, src) \
    asm volatile("cp.async.cg.shared.global [%0], [%1], 16;" :: "r"(dst), "l"(src) : "memory")
#define CP_COMMIT() asm volatile("cp.async.commit_group;" ::: "memory")
#define CP_WAIT2()  asm volatile("cp.async.wait_group 2;" ::: "memory")

#define LDSM_X4(r0, r1, r2, r3, addr) \
    asm volatile("ldmatrix.sync.aligned.m8n8.x4.shared.b16 {%0,%1,%2,%3}, [%4];" \
        : "=r"(r0), "=r"(r1), "=r"(r2), "=r"(r3) : "r"(addr))

#define MMA16816(d, a, b) \
    asm volatile("mma.sync.aligned.m16n8k16.row.col.f32.f16.f16.f32 " \
        "{%0,%1,%2,%3},{%4,%5,%6,%7},{%8,%9},{%0,%1,%2,%3};" \
        : "+f"((d)[0]), "+f"((d)[1]), "+f"((d)[2]), "+f"((d)[3]) \
        : "r"((a)[0]), "r"((a)[1]), "r"((a)[2]), "r"((a)[3]), "r"((b)[0]), "r"((b)[1]))

__device__ __forceinline__ float sigmoid_f(float x) {
    return __fdividef(1.0f, 1.0f + __expf(-x));
}
__device__ __forceinline__ float tanh_f(float x) {
    return __fdividef(2.0f, 1.0f + __expf(-2.0f * x)) - 1.0f;
}

// =====================================================================
// Prep 1: A = concat(x1,x2) -> fp16
// =====================================================================
__global__ __launch_bounds__(256)
void conv_a_kernel(const float* __restrict__ x1, const float* __restrict__ x2)
{
    size_t i4 = (size_t)blockIdx.x * 256 + threadIdx.x;   // 8388608 chunks of 4
    int m  = (int)(i4 >> 7);
    int c4 = ((int)i4 & 127) * 4;
    float4 v;
    if (c4 < IN1) v = *(const float4*)(x1 + (size_t)m * IN1 + c4);
    else          v = *(const float4*)(x2 + (size_t)m * IN2 + (c4 - IN1));
    size_t o = (size_t)m * KDIM + c4;
    *(__half2*)&g_Ah[o]     = __floats2half2_rn(v.x, v.y);
    *(__half2*)&g_Ah[o + 2] = __floats2half2_rn(v.z, v.w);
}

// =====================================================================
// Prep 2: W1 [512,1152] -> transposed fp16, layout n' = (j/16)*48 + g*16 + j%16
// =====================================================================
__global__ __launch_bounds__(256)
void conv_w1_kernel(const float* __restrict__ W)
{
    int idx = blockIdx.x * 256 + threadIdx.x;   // < 589824
    int k = idx / N1, c = idx % N1;
    int g = c / G1U, j = c % G1U;
    int n = (j >> 4) * 48 + g * 16 + (j & 15);
    g_Bh[(size_t)n * KDIM + k] = __float2half_rn(W[idx]);
}

// =====================================================================
// Prep 3: W2 [384,48] -> transposed fp16
// =====================================================================
__global__ __launch_bounds__(256)
void conv_w2_kernel(const float* __restrict__ W)
{
    int idx = blockIdx.x * 256 + threadIdx.x;   // < 18432
    if (idx >= G1U * 48) return;
    int k = idx / 48, c = idx % 48;
    g_B2[(size_t)c * G1U + k] = __float2half_rn(W[idx]);
}

// =====================================================================
// GEMM1: h1 = GRU1(A, h=0).  fp16 single-pass HMMA.
// CTA tile 128 x 96; 8 warps of 32x48.  K = 512 -> 8 tiles of 64.
// 3-stage cp.async pipeline, 2 CTAs/SM (16 warps resident).
// =====================================================================
#define G1_STAGE  28672            // 16KB A + 12KB B
#define G1_OFFB   16384
#define G1_NSTG   3
#define G1_BIAS   (G1_NSTG * G1_STAGE) // 86016
#define G1_SMEM   (G1_BIAS + 512)

__device__ __forceinline__ void load_stage_g1(u32 sb, int s, int kt, int m0, int nb, int tid)
{
    const int k0 = kt * 64;
    const u32 base = sb + s * G1_STAGE;
    const char* Ap = (const char*)g_Ah;
    const char* Bp = (const char*)g_Bh;
    // A tile: 128 rows x 128B
#pragma unroll
    for (int i = 0; i < 4; ++i) {
        int c = tid + i * 256;              // 0..1023
        int row = c >> 3, cb = c & 7;
        u32 dst = base + swz(row * 128 + cb * 16);
        const char* src = Ap + (size_t)(m0 + row) * (KDIM * 2) + k0 * 2 + cb * 16;
        CP_ASYNC16(dst, src);
    }
    // B tile: 96 rows x 128B
#pragma unroll
    for (int i = 0; i < 3; ++i) {
        int c = tid + i * 256;              // 0..767
        int row = c >> 3, cb = c & 7;
        u32 dst = base + G1_OFFB + swz(row * 128 + cb * 16);
        const char* src = Bp + (size_t)(nb * 96 + row) * (KDIM * 2) + k0 * 2 + cb * 16;
        CP_ASYNC16(dst, src);
    }
}

__global__ __launch_bounds__(256, 2)
void gemm1_mma_kernel(const float* __restrict__ bias)
{
    extern __shared__ char smem[];
    const u32 sb = smem_u32(smem);
    const int tid  = threadIdx.x;
    const int warp = tid >> 5, lane = tid & 31;
    const int wm = warp & 3;          // m block: 32*wm
    const int wn = warp >> 2;         // n block: 48*wn
    const int nb = blockIdx.x;        // 0..11  (32-unit block)
    const int m0 = blockIdx.y * 128;

    // stage combined biases (32 units for this CTA)
    float* czs  = (float*)(smem + G1_BIAS);
    float* crs  = czs + 32;
    float* ch0s = czs + 64;
    float* ch1s = czs + 96;
    if (tid < 32) {
        int j = nb * 32 + tid;
        czs[tid]  = bias[j]         + bias[N1 + j];
        crs[tid]  = bias[G1U + j]   + bias[N1 + G1U + j];
        ch0s[tid] = bias[2 * G1U + j];
        ch1s[tid] = bias[N1 + 2 * G1U + j];
    }

    float acc[2][6][4];
#pragma unroll
    for (int mi = 0; mi < 2; ++mi)
#pragma unroll
        for (int ni = 0; ni < 6; ++ni)
#pragma unroll
            for (int e = 0; e < 4; ++e) acc[mi][ni][e] = 0.f;

    const int a_row = 32 * wm + (lane & 15);
    const int a_kb  = (lane & 16) ? 16 : 0;
    const int b_row = 48 * wn + (lane & 7) + ((lane & 16) ? 8 : 0);
    const int b_kb  = (lane & 8) ? 16 : 0;

    // prologue: fill stages 0,1
    load_stage_g1(sb, 0, 0, m0, nb, tid); CP_COMMIT();
    load_stage_g1(sb, 1, 1, m0, nb, tid); CP_COMMIT();

    for (int kt = 0; kt < 8; ++kt) {
        const int s = kt % G1_NSTG;
        if (kt + 2 < 8) load_stage_g1(sb, (kt + 2) % G1_NSTG, kt + 2, m0, nb, tid);
        CP_COMMIT();
        CP_WAIT2();
        __syncthreads();

        const u32 abase = sb + s * G1_STAGE;
        const u32 bbase = abase + G1_OFFB;
#pragma unroll
        for (int ks = 0; ks < 4; ++ks) {
            u32 af[2][4], bf[3][4];
#pragma unroll
            for (int mi = 0; mi < 2; ++mi) {
                u32 ad = abase + swz((u32)(a_row + mi * 16) * 128 + ks * 32 + a_kb);
                LDSM_X4(af[mi][0], af[mi][1], af[mi][2], af[mi][3], ad);
            }
#pragma unroll
            for (int bi = 0; bi < 3; ++bi) {
                u32 bd = bbase + swz((u32)(b_row + bi * 16) * 128 + ks * 32 + b_kb);
                LDSM_X4(bf[bi][0], bf[bi][1], bf[bi][2], bf[bi][3], bd);
            }
#pragma unroll
            for (int mi = 0; mi < 2; ++mi)
#pragma unroll
                for (int bi = 0; bi < 3; ++bi) {
                    MMA16816(acc[mi][2 * bi],     af[mi], (&bf[bi][0]));
                    MMA16816(acc[mi][2 * bi + 1], af[mi], (&bf[bi][2]));
                }
        }
        __syncthreads();
    }

    // ---- fused GRU epilogue ----
    const int qr = lane >> 2, qc = lane & 3;
#pragma unroll
    for (int mi = 0; mi < 2; ++mi) {
#pragma unroll
        for (int nip = 0; nip < 2; ++nip) {
            const int ul = wn * 16 + 8 * nip + 2 * qc;   // 0..31
            const int j0 = nb * 32 + ul;
            const float cz0 = czs[ul],  cz1 = czs[ul + 1];
            const float cr0 = crs[ul],  cr1 = crs[ul + 1];
            const float c00 = ch0s[ul], c01 = ch0s[ul + 1];
            const float c10 = ch1s[ul], c11 = ch1s[ul + 1];
            const float* az = acc[mi][nip];
            const float* ar = acc[mi][nip + 2];
            const float* ah = acc[mi][nip + 4];
#pragma unroll
            for (int half = 0; half < 2; ++half) {
                const int row = m0 + 32 * wm + 16 * mi + qr + half * 8;
                float z0 = sigmoid_f(az[2 * half]     + cz0);
                float z1 = sigmoid_f(az[2 * half + 1] + cz1);
                float r0 = sigmoid_f(ar[2 * half]     + cr0);
                float r1 = sigmoid_f(ar[2 * half + 1] + cr1);
                float h0 = tanh_f(ah[2 * half]     + c00 + r0 * c10);
                float h1 = tanh_f(ah[2 * half + 1] + c01 + r1 * c11);
                *(__half2*)&g_h1h[(size_t)row * G1U + j0] =
                    __floats2half2_rn((1.f - z0) * h0, (1.f - z1) * h1);
            }
        }
    }
}

// =====================================================================
// GEMM2: h2 = GRU2(h1, h=0).  fp16 single-pass HMMA.
// CTA tile 128 x 48; 8 warps of 16x48. K = 384 -> 6 tiles; 3-stage pipeline.
// =====================================================================
#define G2_STAGE  22528          // 16KB A + 6KB B (padded)
#define G2_OFFB   16384
#define G2_BIAS   (3 * G2_STAGE) // 67584
#define G2_SMEM   (G2_BIAS + 512)

__device__ __forceinline__ void load_stage_g2(u32 sb, int s, int kt, int m0, int tid)
{
    const int k0 = kt * 64;
    const u32 base = sb + s * G2_STAGE;
    const char* Ap = (const char*)g_h1h;
    const char* Bp = (const char*)g_B2;
#pragma unroll
    for (int i = 0; i < 4; ++i) {
        int c = tid + i * 256;              // 0..1023
        int row = c >> 3, cb = c & 7;
        u32 dst = base + swz(row * 128 + cb * 16);
        const char* src = Ap + (size_t)(m0 + row) * (G1U * 2) + k0 * 2 + cb * 16;
        CP_ASYNC16(dst, src);
    }
#pragma unroll
    for (int i = 0; i < 2; ++i) {
        int c = tid + i * 256;
        if (c < 384) {
            int row = c >> 3, cb = c & 7;
            u32 dst = base + G2_OFFB + swz(row * 128 + cb * 16);
            const char* src = Bp + (size_t)row * (G1U * 2) + k0 * 2 + cb * 16;
            CP_ASYNC16(dst, src);
        }
    }
}

__global__ __launch_bounds__(256, 2)
void gemm2_mma_kernel(const float* __restrict__ bias)
{
    extern __shared__ char smem[];
    const u32 sb = smem_u32(smem);
    const int tid  = threadIdx.x;
    const int warp = tid >> 5, lane = tid & 31;
    const int m0 = blockIdx.x * 128;

    float* czs  = (float*)(smem + G2_BIAS);
    float* crs  = czs + 16;
    float* ch0s = czs + 32;
    float* ch1s = czs + 48;
    if (tid < 16) {
        czs[tid]  = bias[tid]      + bias[48 + tid];
        crs[tid]  = bias[16 + tid] + bias[64 + tid];
        ch0s[tid] = bias[32 + tid];
        ch1s[tid] = bias[80 + tid];
    }

    float acc[6][4];
#pragma unroll
    for (int ni = 0; ni < 6; ++ni)
#pragma unroll
        for (int e = 0; e < 4; ++e) acc[ni][e] = 0.f;

    const int a_row = 16 * warp + (lane & 15);
    const int a_kb  = (lane & 16) ? 16 : 0;
    const int b_row = (lane & 7) + ((lane & 16) ? 8 : 0);
    const int b_kb  = (lane & 8) ? 16 : 0;

    load_stage_g2(sb, 0, 0, m0, tid); CP_COMMIT();
    load_stage_g2(sb, 1, 1, m0, tid); CP_COMMIT();

    for (int kt = 0; kt < 6; ++kt) {
        const int s = kt % 3;
        if (kt + 2 < 6) load_stage_g2(sb, (kt + 2) % 3, kt + 2, m0, tid);
        CP_COMMIT();
        CP_WAIT2();
        __syncthreads();

        const u32 abase = sb + s * G2_STAGE;
        const u32 bbase = abase + G2_OFFB;
#pragma unroll
        for (int ks = 0; ks < 4; ++ks) {
            u32 af[4], bf[3][4];
            u32 ad = abase + swz((u32)a_row * 128 + ks * 32 + a_kb);
            LDSM_X4(af[0], af[1], af[2], af[3], ad);
#pragma unroll
            for (int bi = 0; bi < 3; ++bi) {
                u32 bd = bbase + swz((u32)(b_row + bi * 16) * 128 + ks * 32 + b_kb);
                LDSM_X4(bf[bi][0], bf[bi][1], bf[bi][2], bf[bi][3], bd);
            }
#pragma unroll
            for (int bi = 0; bi < 3; ++bi) {
                MMA16816(acc[2 * bi],     af, (&bf[bi][0]));
                MMA16816(acc[2 * bi + 1], af, (&bf[bi][2]));
            }
        }
        __syncthreads();
    }

    const int qr = lane >> 2, qc = lane & 3;
#pragma unroll
    for (int nip = 0; nip < 2; ++nip) {
        const int u0 = 8 * nip + 2 * qc;
        const float cz0 = czs[u0],  cz1 = czs[u0 + 1];
        const float cr0 = crs[u0],  cr1 = crs[u0 + 1];
        const float c00 = ch0s[u0], c01 = ch0s[u0 + 1];
        const float c10 = ch1s[u0], c11 = ch1s[u0 + 1];
        const float* az = acc[nip];
        const float* ar = acc[nip + 2];
        const float* ah = acc[nip + 4];
#pragma unroll
        for (int half = 0; half < 2; ++half) {
            const int row = m0 + 16 * warp + qr + half * 8;
            float z0 = sigmoid_f(az[2 * half]     + cz0);
            float z1 = sigmoid_f(az[2 * half + 1] + cz1);
            float r0 = sigmoid_f(ar[2 * half]     + cr0);
            float r1 = sigmoid_f(ar[2 * half + 1] + cr1);
            float h0 = tanh_f(ah[2 * half]     + c00 + r0 * c10);
            float h1 = tanh_f(ah[2 * half + 1] + c01 + r1 * c11);
            *(float2*)&g_h2[(size_t)row * G2U + u0] =
                make_float2((1.f - z0) * h0, (1.f - z1) * h1);
        }
    }
}

// =====================================================================
// Kernel 3: head + softmax (fp32). One warp per 8 rows (2 at a time).
// =====================================================================
__global__ __launch_bounds__(256)
void head_kernel(const float* __restrict__ w1, const float* __restrict__ b1,
                 const float* __restrict__ w2, const float* __restrict__ b2,
                 const float* __restrict__ gv1, const float* __restrict__ gv2,
                 float* __restrict__ out)
{
    __shared__ float W1s[16 * NLEV];
    __shared__ float W2s[16 * NLEV];
    __shared__ float b1s[NLEV], b2s[NLEV], g1s[NLEV], g2s[NLEV];

    const int t = threadIdx.x;
    for (int i = t; i < 16 * NLEV; i += 256) { W1s[i] = w1[i]; W2s[i] = w2[i]; }
    b1s[t] = b1[t]; b2s[t] = b2[t]; g1s[t] = gv1[t]; g2s[t] = gv2[t];
    __syncthreads();

    const int warp = t >> 5, lane = t & 31;
    const int gwarp = blockIdx.x * 8 + warp;

    for (int p = 0; p < 4; ++p) {
        const int r0 = gwarp * 8 + p * 2;
        float ha[16], hb[16];
        {
            const float4* pa = (const float4*)&g_h2[(size_t)r0 * G2U];
            const float4* pb = (const float4*)&g_h2[(size_t)(r0 + 1) * G2U];
#pragma unroll
            for (int i = 0; i < 4; ++i) {
                float4 va = __ldg(pa + i);
                float4 vb = __ldg(pb + i);
                ha[4*i] = va.x; ha[4*i+1] = va.y; ha[4*i+2] = va.z; ha[4*i+3] = va.w;
                hb[4*i] = vb.x; hb[4*i+1] = vb.y; hb[4*i+2] = vb.z; hb[4*i+3] = vb.w;
            }
        }
        float a1a[8], a2a[8], a1b[8], a2b[8];
#pragma unroll
        for (int q = 0; q < 8; ++q) { a1a[q]=0.f; a2a[q]=0.f; a1b[q]=0.f; a2b[q]=0.f; }
#pragma unroll
        for (int k = 0; k < 16; ++k) {
            const float hka = ha[k], hkb = hb[k];
#pragma unroll
            for (int q = 0; q < 8; ++q) {
                const int l = lane + 32 * q;
                const float wv1 = W1s[k * NLEV + l];
                const float wv2 = W2s[k * NLEV + l];
                a1a[q] = fmaf(hka, wv1, a1a[q]);
                a2a[q] = fmaf(hka, wv2, a2a[q]);
                a1b[q] = fmaf(hkb, wv1, a1b[q]);
                a2b[q] = fmaf(hkb, wv2, a2b[q]);
            }
        }
#pragma unroll
        for (int ri = 0; ri < 2; ++ri) {
            float v[8];
#pragma unroll
            for (int q = 0; q < 8; ++q) {
                const int l = lane + 32 * q;
                const float t1 = tanh_f((ri ? a1b[q] : a1a[q]) + b1s[l]);
                const float t2 = tanh_f((ri ? a2b[q] : a2a[q]) + b2s[l]);
                v[q] = g1s[l] * t1 + g2s[l] * t2;
            }
            float mx = v[0];
#pragma unroll
            for (int q = 1; q < 8; ++q) mx = fmaxf(mx, v[q]);
#pragma unroll
            for (int off = 16; off >= 1; off >>= 1)
                mx = fmaxf(mx, __shfl_xor_sync(0xffffffffu, mx, off));
            float e[8], s = 0.f;
#pragma unroll
            for (int q = 0; q < 8; ++q) { e[q] = __expf(v[q] - mx); s += e[q]; }
#pragma unroll
            for (int off = 16; off >= 1; off >>= 1)
                s += __shfl_xor_sync(0xffffffffu, s, off);
            const float inv = 1.0f / s;
            float* orow = out + (size_t)(r0 + ri) * NLEV;
#pragma unroll
            for (int q = 0; q < 8; ++q)
                orow[lane + 32 * q] = e[q] * inv;
        }
    }
}

// =====================================================================
extern "C" void kernel_launch(void* const* d_in, const int* in_sizes, int n_in,
                              void* d_out, int out_size)
{
    const float* x1   = (const float*)d_in[0];
    const float* x2   = (const float*)d_in[1];
    const float* g1k  = (const float*)d_in[2];
    const float* g1b  = (const float*)d_in[4];
    const float* g2k  = (const float*)d_in[5];
    const float* g2b  = (const float*)d_in[7];
    const float* fw1  = (const float*)d_in[8];
    const float* fb1  = (const float*)d_in[9];
    const float* fw2  = (const float*)d_in[10];
    const float* fb2  = (const float*)d_in[11];
    const float* fg1  = (const float*)d_in[12];
    const float* fg2  = (const float*)d_in[13];
    float* out = (float*)d_out;

    cudaFuncSetAttribute(gemm1_mma_kernel,
                         cudaFuncAttributeMaxDynamicSharedMemorySize, G1_SMEM);
    cudaFuncSetAttribute(gemm2_mma_kernel,
                         cudaFuncAttributeMaxDynamicSharedMemorySize, G2_SMEM);

    conv_a_kernel<<<(NB * (KDIM / 4)) / 256, 256>>>(x1, x2);
    conv_w1_kernel<<<(KDIM * N1) / 256, 256>>>(g1k);
    conv_w2_kernel<<<(G1U * 48 + 255) / 256, 256>>>(g2k);
    gemm1_mma_kernel<<<dim3(12, NB / 128), 256, G1_SMEM>>>(g1b);
    gemm2_mma_kernel<<<NB / 128, 256, G2_SMEM>>>(g2b);
    head_kernel<<<NB / 64, 256>>>(fw1, fb1, fw2, fb2, fg1, fg2, out);
}

// round 6
// speedup vs baseline: 6.4947x; 1.0129x over previous
#include <cuda_runtime.h>
#include <cuda_fp16.h>
#include <cstdint>

// ---------------- problem constants ----------------
#define NB     65536
#define IN1    384
#define IN2    128
#define KDIM   512
#define G1U    384
#define N1     1152
#define G2U    16
#define NLEV   256

typedef unsigned long long u64;
typedef unsigned int u32;

// ---------------- device scratch ----------------
__device__ __half g_Ah[(size_t)NB * KDIM];     // 64 MB  fp16 concat(x1,x2)
__device__ __half g_Bh[(size_t)N1 * KDIM];     // reordered+transposed W1
__device__ __half g_h1h[(size_t)NB * G1U];     // 48 MB  fp16 h1
__device__ __half g_B2[(size_t)48 * G1U];      // transposed W2
__device__ float  g_h2[(size_t)NB * G2U];      // 4 MB   fp32 h2

// ---------------- helpers ----------------
__device__ __forceinline__ u32 smem_u32(const void* p) {
    u32 a;
    asm("{ .reg .u64 t; cvta.to.shared.u64 t, %1; cvt.u32.u64 %0, t; }" : "=r"(a) : "l"(p));
    return a;
}
__device__ __forceinline__ u32 swz(u32 x) { return x ^ ((x >> 3) & 0x70); }

#define CP_ASYNC16(dst, src) \
    asm volatile("cp.async.cg.shared.global [%0], [%1], 16;" :: "r"(dst), "l"(src) : "memory")
#define CP_COMMIT() asm volatile("cp.async.commit_group;" ::: "memory")
#define CP_WAIT1()  asm volatile("cp.async.wait_group 1;" ::: "memory")

#define LDSM_X4(r0, r1, r2, r3, addr) \
    asm volatile("ldmatrix.sync.aligned.m8n8.x4.shared.b16 {%0,%1,%2,%3}, [%4];" \
        : "=r"(r0), "=r"(r1), "=r"(r2), "=r"(r3) : "r"(addr))

#define MMA16816(d, a, b) \
    asm volatile("mma.sync.aligned.m16n8k16.row.col.f32.f16.f16.f32 " \
        "{%0,%1,%2,%3},{%4,%5,%6,%7},{%8,%9},{%0,%1,%2,%3};" \
        : "+f"((d)[0]), "+f"((d)[1]), "+f"((d)[2]), "+f"((d)[3]) \
        : "r"((a)[0]), "r"((a)[1]), "r"((a)[2]), "r"((a)[3]), "r"((b)[0]), "r"((b)[1]))

__device__ __forceinline__ float sigmoid_f(float x) {
    return __fdividef(1.0f, 1.0f + __expf(-x));
}
__device__ __forceinline__ float tanh_f(float x) {
    return __fdividef(2.0f, 1.0f + __expf(-2.0f * x)) - 1.0f;
}

// =====================================================================
// Prep 1: A = concat(x1,x2) -> fp16
// =====================================================================
__global__ __launch_bounds__(256)
void conv_a_kernel(const float* __restrict__ x1, const float* __restrict__ x2)
{
    size_t i4 = (size_t)blockIdx.x * 256 + threadIdx.x;   // 8388608 chunks of 4
    int m  = (int)(i4 >> 7);
    int c4 = ((int)i4 & 127) * 4;
    float4 v;
    if (c4 < IN1) v = *(const float4*)(x1 + (size_t)m * IN1 + c4);
    else          v = *(const float4*)(x2 + (size_t)m * IN2 + (c4 - IN1));
    size_t o = (size_t)m * KDIM + c4;
    *(__half2*)&g_Ah[o]     = __floats2half2_rn(v.x, v.y);
    *(__half2*)&g_Ah[o + 2] = __floats2half2_rn(v.z, v.w);
}

// =====================================================================
// Prep 2: W1 [512,1152] -> transposed fp16, layout n' = (j/16)*48 + g*16 + j%16
// =====================================================================
__global__ __launch_bounds__(256)
void conv_w1_kernel(const float* __restrict__ W)
{
    int idx = blockIdx.x * 256 + threadIdx.x;   // < 589824
    int k = idx / N1, c = idx % N1;
    int g = c / G1U, j = c % G1U;
    int n = (j >> 4) * 48 + g * 16 + (j & 15);
    g_Bh[(size_t)n * KDIM + k] = __float2half_rn(W[idx]);
}

// =====================================================================
// Prep 3: W2 [384,48] -> transposed fp16
// =====================================================================
__global__ __launch_bounds__(256)
void conv_w2_kernel(const float* __restrict__ W)
{
    int idx = blockIdx.x * 256 + threadIdx.x;   // < 18432
    if (idx >= G1U * 48) return;
    int k = idx / 48, c = idx % 48;
    g_B2[(size_t)c * G1U + k] = __float2half_rn(W[idx]);
}

// =====================================================================
// GEMM1: h1 = GRU1(A, h=0).  fp16 single-pass HMMA.
// CTA tile 128 x 96; 8 warps of 32x48.  K = 512 -> 8 tiles of 64.
// 3-stage cp.async pipeline, ONE barrier per k-tile (loads issued
// post-barrier; 3-stage rotation makes the trailing barrier redundant).
// =====================================================================
#define G1_STAGE  28672            // 16KB A + 12KB B
#define G1_OFFB   16384
#define G1_NSTG   3
#define G1_BIAS   (G1_NSTG * G1_STAGE) // 86016
#define G1_SMEM   (G1_BIAS + 512)

__device__ __forceinline__ void load_stage_g1(u32 sb, int s, int kt, int m0, int nb, int tid)
{
    const int k0 = kt * 64;
    const u32 base = sb + s * G1_STAGE;
    const char* Ap = (const char*)g_Ah;
    const char* Bp = (const char*)g_Bh;
    // A tile: 128 rows x 128B
#pragma unroll
    for (int i = 0; i < 4; ++i) {
        int c = tid + i * 256;              // 0..1023
        int row = c >> 3, cb = c & 7;
        u32 dst = base + swz(row * 128 + cb * 16);
        const char* src = Ap + (size_t)(m0 + row) * (KDIM * 2) + k0 * 2 + cb * 16;
        CP_ASYNC16(dst, src);
    }
    // B tile: 96 rows x 128B
#pragma unroll
    for (int i = 0; i < 3; ++i) {
        int c = tid + i * 256;              // 0..767
        int row = c >> 3, cb = c & 7;
        u32 dst = base + G1_OFFB + swz(row * 128 + cb * 16);
        const char* src = Bp + (size_t)(nb * 96 + row) * (KDIM * 2) + k0 * 2 + cb * 16;
        CP_ASYNC16(dst, src);
    }
}

__global__ __launch_bounds__(256, 2)
void gemm1_mma_kernel(const float* __restrict__ bias)
{
    extern __shared__ char smem[];
    const u32 sb = smem_u32(smem);
    const int tid  = threadIdx.x;
    const int warp = tid >> 5, lane = tid & 31;
    const int wm = warp & 3;          // m block: 32*wm
    const int wn = warp >> 2;         // n block: 48*wn
    const int nb = blockIdx.x;        // 0..11  (32-unit block)
    const int m0 = blockIdx.y * 128;

    // stage combined biases (32 units for this CTA)
    float* czs  = (float*)(smem + G1_BIAS);
    float* crs  = czs + 32;
    float* ch0s = czs + 64;
    float* ch1s = czs + 96;
    if (tid < 32) {
        int j = nb * 32 + tid;
        czs[tid]  = bias[j]         + bias[N1 + j];
        crs[tid]  = bias[G1U + j]   + bias[N1 + G1U + j];
        ch0s[tid] = bias[2 * G1U + j];
        ch1s[tid] = bias[N1 + 2 * G1U + j];
    }

    float acc[2][6][4];
#pragma unroll
    for (int mi = 0; mi < 2; ++mi)
#pragma unroll
        for (int ni = 0; ni < 6; ++ni)
#pragma unroll
            for (int e = 0; e < 4; ++e) acc[mi][ni][e] = 0.f;

    const int a_row = 32 * wm + (lane & 15);
    const int a_kb  = (lane & 16) ? 16 : 0;
    const int b_row = 48 * wn + (lane & 7) + ((lane & 16) ? 8 : 0);
    const int b_kb  = (lane & 8) ? 16 : 0;

    // prologue: fill stages 0,1
    load_stage_g1(sb, 0, 0, m0, nb, tid); CP_COMMIT();
    load_stage_g1(sb, 1, 1, m0, nb, tid); CP_COMMIT();

    for (int kt = 0; kt < 8; ++kt) {
        const int s = kt % G1_NSTG;
        // stage kt done when <=1 newer group pending
        CP_WAIT1();
        __syncthreads();
        // issue next prefetch AFTER barrier: fast warps can't clobber a
        // stage that slower warps still read (they'd have to pass the
        // NEXT barrier first, which the readers gate).
        if (kt + 2 < 8) load_stage_g1(sb, (kt + 2) % G1_NSTG, kt + 2, m0, nb, tid);
        CP_COMMIT();

        const u32 abase = sb + s * G1_STAGE;
        const u32 bbase = abase + G1_OFFB;
#pragma unroll
        for (int ks = 0; ks < 4; ++ks) {
            u32 af[2][4], bf[3][4];
#pragma unroll
            for (int mi = 0; mi < 2; ++mi) {
                u32 ad = abase + swz((u32)(a_row + mi * 16) * 128 + ks * 32 + a_kb);
                LDSM_X4(af[mi][0], af[mi][1], af[mi][2], af[mi][3], ad);
            }
#pragma unroll
            for (int bi = 0; bi < 3; ++bi) {
                u32 bd = bbase + swz((u32)(b_row + bi * 16) * 128 + ks * 32 + b_kb);
                LDSM_X4(bf[bi][0], bf[bi][1], bf[bi][2], bf[bi][3], bd);
            }
#pragma unroll
            for (int mi = 0; mi < 2; ++mi)
#pragma unroll
                for (int bi = 0; bi < 3; ++bi) {
                    MMA16816(acc[mi][2 * bi],     af[mi], (&bf[bi][0]));
                    MMA16816(acc[mi][2 * bi + 1], af[mi], (&bf[bi][2]));
                }
        }
        // no trailing barrier
    }

    // ---- fused GRU epilogue ----
    const int qr = lane >> 2, qc = lane & 3;
#pragma unroll
    for (int mi = 0; mi < 2; ++mi) {
#pragma unroll
        for (int nip = 0; nip < 2; ++nip) {
            const int ul = wn * 16 + 8 * nip + 2 * qc;   // 0..31
            const int j0 = nb * 32 + ul;
            const float cz0 = czs[ul],  cz1 = czs[ul + 1];
            const float cr0 = crs[ul],  cr1 = crs[ul + 1];
            const float c00 = ch0s[ul], c01 = ch0s[ul + 1];
            const float c10 = ch1s[ul], c11 = ch1s[ul + 1];
            const float* az = acc[mi][nip];
            const float* ar = acc[mi][nip + 2];
            const float* ah = acc[mi][nip + 4];
#pragma unroll
            for (int half = 0; half < 2; ++half) {
                const int row = m0 + 32 * wm + 16 * mi + qr + half * 8;
                float z0 = sigmoid_f(az[2 * half]     + cz0);
                float z1 = sigmoid_f(az[2 * half + 1] + cz1);
                float r0 = sigmoid_f(ar[2 * half]     + cr0);
                float r1 = sigmoid_f(ar[2 * half + 1] + cr1);
                float h0 = tanh_f(ah[2 * half]     + c00 + r0 * c10);
                float h1 = tanh_f(ah[2 * half + 1] + c01 + r1 * c11);
                *(__half2*)&g_h1h[(size_t)row * G1U + j0] =
                    __floats2half2_rn((1.f - z0) * h0, (1.f - z1) * h1);
            }
        }
    }
}

// =====================================================================
// GEMM2: h2 = GRU2(h1, h=0).  fp16 single-pass HMMA.
// CTA tile 128 x 48; 8 warps of 16x48. K = 384 -> 6 tiles; 3-stage,
// one barrier per k-tile (same scheme as gemm1).
// =====================================================================
#define G2_STAGE  22528          // 16KB A + 6KB B (padded)
#define G2_OFFB   16384
#define G2_BIAS   (3 * G2_STAGE) // 67584
#define G2_SMEM   (G2_BIAS + 512)

__device__ __forceinline__ void load_stage_g2(u32 sb, int s, int kt, int m0, int tid)
{
    const int k0 = kt * 64;
    const u32 base = sb + s * G2_STAGE;
    const char* Ap = (const char*)g_h1h;
    const char* Bp = (const char*)g_B2;
#pragma unroll
    for (int i = 0; i < 4; ++i) {
        int c = tid + i * 256;              // 0..1023
        int row = c >> 3, cb = c & 7;
        u32 dst = base + swz(row * 128 + cb * 16);
        const char* src = Ap + (size_t)(m0 + row) * (G1U * 2) + k0 * 2 + cb * 16;
        CP_ASYNC16(dst, src);
    }
#pragma unroll
    for (int i = 0; i < 2; ++i) {
        int c = tid + i * 256;
        if (c < 384) {
            int row = c >> 3, cb = c & 7;
            u32 dst = base + G2_OFFB + swz(row * 128 + cb * 16);
            const char* src = Bp + (size_t)row * (G1U * 2) + k0 * 2 + cb * 16;
            CP_ASYNC16(dst, src);
        }
    }
}

__global__ __launch_bounds__(256, 2)
void gemm2_mma_kernel(const float* __restrict__ bias)
{
    extern __shared__ char smem[];
    const u32 sb = smem_u32(smem);
    const int tid  = threadIdx.x;
    const int warp = tid >> 5, lane = tid & 31;
    const int m0 = blockIdx.x * 128;

    float* czs  = (float*)(smem + G2_BIAS);
    float* crs  = czs + 16;
    float* ch0s = czs + 32;
    float* ch1s = czs + 48;
    if (tid < 16) {
        czs[tid]  = bias[tid]      + bias[48 + tid];
        crs[tid]  = bias[16 + tid] + bias[64 + tid];
        ch0s[tid] = bias[32 + tid];
        ch1s[tid] = bias[80 + tid];
    }

    float acc[6][4];
#pragma unroll
    for (int ni = 0; ni < 6; ++ni)
#pragma unroll
        for (int e = 0; e < 4; ++e) acc[ni][e] = 0.f;

    const int a_row = 16 * warp + (lane & 15);
    const int a_kb  = (lane & 16) ? 16 : 0;
    const int b_row = (lane & 7) + ((lane & 16) ? 8 : 0);
    const int b_kb  = (lane & 8) ? 16 : 0;

    load_stage_g2(sb, 0, 0, m0, tid); CP_COMMIT();
    load_stage_g2(sb, 1, 1, m0, tid); CP_COMMIT();

    for (int kt = 0; kt < 6; ++kt) {
        const int s = kt % 3;
        CP_WAIT1();
        __syncthreads();
        if (kt + 2 < 6) load_stage_g2(sb, (kt + 2) % 3, kt + 2, m0, tid);
        CP_COMMIT();

        const u32 abase = sb + s * G2_STAGE;
        const u32 bbase = abase + G2_OFFB;
#pragma unroll
        for (int ks = 0; ks < 4; ++ks) {
            u32 af[4], bf[3][4];
            u32 ad = abase + swz((u32)a_row * 128 + ks * 32 + a_kb);
            LDSM_X4(af[0], af[1], af[2], af[3], ad);
#pragma unroll
            for (int bi = 0; bi < 3; ++bi) {
                u32 bd = bbase + swz((u32)(b_row + bi * 16) * 128 + ks * 32 + b_kb);
                LDSM_X4(bf[bi][0], bf[bi][1], bf[bi][2], bf[bi][3], bd);
            }
#pragma unroll
            for (int bi = 0; bi < 3; ++bi) {
                MMA16816(acc[2 * bi],     af, (&bf[bi][0]));
                MMA16816(acc[2 * bi + 1], af, (&bf[bi][2]));
            }
        }
    }

    const int qr = lane >> 2, qc = lane & 3;
#pragma unroll
    for (int nip = 0; nip < 2; ++nip) {
        const int u0 = 8 * nip + 2 * qc;
        const float cz0 = czs[u0],  cz1 = czs[u0 + 1];
        const float cr0 = crs[u0],  cr1 = crs[u0 + 1];
        const float c00 = ch0s[u0], c01 = ch0s[u0 + 1];
        const float c10 = ch1s[u0], c11 = ch1s[u0 + 1];
        const float* az = acc[nip];
        const float* ar = acc[nip + 2];
        const float* ah = acc[nip + 4];
#pragma unroll
        for (int half = 0; half < 2; ++half) {
            const int row = m0 + 16 * warp + qr + half * 8;
            float z0 = sigmoid_f(az[2 * half]     + cz0);
            float z1 = sigmoid_f(az[2 * half + 1] + cz1);
            float r0 = sigmoid_f(ar[2 * half]     + cr0);
            float r1 = sigmoid_f(ar[2 * half + 1] + cr1);
            float h0 = tanh_f(ah[2 * half]     + c00 + r0 * c10);
            float h1 = tanh_f(ah[2 * half + 1] + c01 + r1 * c11);
            *(float2*)&g_h2[(size_t)row * G2U + u0] =
                make_float2((1.f - z0) * h0, (1.f - z1) * h1);
        }
    }
}

// =====================================================================
// Kernel 3: head + softmax (fp32). One warp per 8 rows (2 at a time).
// =====================================================================
__global__ __launch_bounds__(256)
void head_kernel(const float* __restrict__ w1, const float* __restrict__ b1,
                 const float* __restrict__ w2, const float* __restrict__ b2,
                 const float* __restrict__ gv1, const float* __restrict__ gv2,
                 float* __restrict__ out)
{
    __shared__ float W1s[16 * NLEV];
    __shared__ float W2s[16 * NLEV];
    __shared__ float b1s[NLEV], b2s[NLEV], g1s[NLEV], g2s[NLEV];

    const int t = threadIdx.x;
    for (int i = t; i < 16 * NLEV; i += 256) { W1s[i] = w1[i]; W2s[i] = w2[i]; }
    b1s[t] = b1[t]; b2s[t] = b2[t]; g1s[t] = gv1[t]; g2s[t] = gv2[t];
    __syncthreads();

    const int warp = t >> 5, lane = t & 31;
    const int gwarp = blockIdx.x * 8 + warp;

    for (int p = 0; p < 4; ++p) {
        const int r0 = gwarp * 8 + p * 2;
        float ha[16], hb[16];
        {
            const float4* pa = (const float4*)&g_h2[(size_t)r0 * G2U];
            const float4* pb = (const float4*)&g_h2[(size_t)(r0 + 1) * G2U];
#pragma unroll
            for (int i = 0; i < 4; ++i) {
                float4 va = __ldg(pa + i);
                float4 vb = __ldg(pb + i);
                ha[4*i] = va.x; ha[4*i+1] = va.y; ha[4*i+2] = va.z; ha[4*i+3] = va.w;
                hb[4*i] = vb.x; hb[4*i+1] = vb.y; hb[4*i+2] = vb.z; hb[4*i+3] = vb.w;
            }
        }
        float a1a[8], a2a[8], a1b[8], a2b[8];
#pragma unroll
        for (int q = 0; q < 8; ++q) { a1a[q]=0.f; a2a[q]=0.f; a1b[q]=0.f; a2b[q]=0.f; }
#pragma unroll
        for (int k = 0; k < 16; ++k) {
            const float hka = ha[k], hkb = hb[k];
#pragma unroll
            for (int q = 0; q < 8; ++q) {
                const int l = lane + 32 * q;
                const float wv1 = W1s[k * NLEV + l];
                const float wv2 = W2s[k * NLEV + l];
                a1a[q] = fmaf(hka, wv1, a1a[q]);
                a2a[q] = fmaf(hka, wv2, a2a[q]);
                a1b[q] = fmaf(hkb, wv1, a1b[q]);
                a2b[q] = fmaf(hkb, wv2, a2b[q]);
            }
        }
#pragma unroll
        for (int ri = 0; ri < 2; ++ri) {
            float v[8];
#pragma unroll
            for (int q = 0; q < 8; ++q) {
                const int l = lane + 32 * q;
                const float t1 = tanh_f((ri ? a1b[q] : a1a[q]) + b1s[l]);
                const float t2 = tanh_f((ri ? a2b[q] : a2a[q]) + b2s[l]);
                v[q] = g1s[l] * t1 + g2s[l] * t2;
            }
            float mx = v[0];
#pragma unroll
            for (int q = 1; q < 8; ++q) mx = fmaxf(mx, v[q]);
#pragma unroll
            for (int off = 16; off >= 1; off >>= 1)
                mx = fmaxf(mx, __shfl_xor_sync(0xffffffffu, mx, off));
            float e[8], s = 0.f;
#pragma unroll
            for (int q = 0; q < 8; ++q) { e[q] = __expf(v[q] - mx); s += e[q]; }
#pragma unroll
            for (int off = 16; off >= 1; off >>= 1)
                s += __shfl_xor_sync(0xffffffffu, s, off);
            const float inv = 1.0f / s;
            float* orow = out + (size_t)(r0 + ri) * NLEV;
#pragma unroll
            for (int q = 0; q < 8; ++q)
                orow[lane + 32 * q] = e[q] * inv;
        }
    }
}

// =====================================================================
extern "C" void kernel_launch(void* const* d_in, const int* in_sizes, int n_in,
                              void* d_out, int out_size)
{
    const float* x1   = (const float*)d_in[0];
    const float* x2   = (const float*)d_in[1];
    const float* g1k  = (const float*)d_in[2];
    const float* g1b  = (const float*)d_in[4];
    const float* g2k  = (const float*)d_in[5];
    const float* g2b  = (const float*)d_in[7];
    const float* fw1  = (const float*)d_in[8];
    const float* fb1  = (const float*)d_in[9];
    const float* fw2  = (const float*)d_in[10];
    const float* fb2  = (const float*)d_in[11];
    const float* fg1  = (const float*)d_in[12];
    const float* fg2  = (const float*)d_in[13];
    float* out = (float*)d_out;

    cudaFuncSetAttribute(gemm1_mma_kernel,
                         cudaFuncAttributeMaxDynamicSharedMemorySize, G1_SMEM);
    cudaFuncSetAttribute(gemm2_mma_kernel,
                         cudaFuncAttributeMaxDynamicSharedMemorySize, G2_SMEM);

    conv_a_kernel<<<(NB * (KDIM / 4)) / 256, 256>>>(x1, x2);
    conv_w1_kernel<<<(KDIM * N1) / 256, 256>>>(g1k);
    conv_w2_kernel<<<(G1U * 48 + 255) / 256, 256>>>(g2k);
    gemm1_mma_kernel<<<dim3(12, NB / 128), 256, G1_SMEM>>>(g1b);
    gemm2_mma_kernel<<<NB / 128, 256, G2_SMEM>>>(g2b);
    head_kernel<<<NB / 64, 256>>>(fw1, fb1, fw2, fb2, fg1, fg2, out);
}